// round 3
// baseline (speedup 1.0000x reference)
#include <cuda_runtime.h>
#include <math.h>

#define D 128
#define NS_MAX 100000
#define NI_MAX 20000
#define E_MAX  600000

// ---------------- device scratch (static, no allocation) ----------------
__device__ float g_aggI[(size_t)NI_MAX * D];
__device__ float g_aggS[(size_t)NS_MAX * D];
__device__ float g_aggP[(size_t)NS_MAX * D];

__device__ int g_off_resp[NI_MAX + 1];
__device__ int g_edge_resp[E_MAX];
__device__ int g_off_rev[NS_MAX + 1];
__device__ int g_edge_rev[E_MAX];
__device__ int g_off_prec[NS_MAX + 1];
__device__ int g_edge_prec[E_MAX];

__device__ int   g_cursor[NS_MAX + 1];
__device__ int   g_bsum[1024];
__device__ float g_colstats[256];   // [0:128) sum, [128:256) sumsq
__device__ float g_bn_ac[256];      // [0:128) a,   [128:256) c

// ---------------- small utility kernels ----------------
__global__ void k_zero_i(int* __restrict__ p, int n) {
    int i = blockIdx.x * blockDim.x + threadIdx.x;
    if (i < n) p[i] = 0;
}
__global__ void k_zero_f(float* __restrict__ p, int n) {
    int i = blockIdx.x * blockDim.x + threadIdx.x;
    if (i < n) p[i] = 0.f;
}
__global__ void k_count(const int* __restrict__ dst, int E, int* __restrict__ cnt) {
    int i = blockIdx.x * blockDim.x + threadIdx.x;
    if (i < E) atomicAdd(&cnt[dst[i]], 1);
}
// block-level inclusive scan; writes off[i+1], block totals to bsum
__global__ void k_scan_block(const int* __restrict__ cnt, int n,
                             int* __restrict__ off, int* __restrict__ bsum) {
    __shared__ int sh[1024];
    int tid = threadIdx.x;
    int i = blockIdx.x * 1024 + tid;
    int v = (i < n) ? cnt[i] : 0;
    sh[tid] = v;
    __syncthreads();
    for (int d = 1; d < 1024; d <<= 1) {
        int t = 0;
        if (tid >= d) t = sh[tid - d];
        __syncthreads();
        if (tid >= d) sh[tid] += t;
        __syncthreads();
    }
    if (i < n) off[i + 1] = sh[tid];
    if (tid == 1023) bsum[blockIdx.x] = sh[1023];
}
// single-block exclusive scan of block sums (nb <= 1024)
__global__ void k_scan_bsum(int* __restrict__ bsum, int nb) {
    __shared__ int sh[1024];
    int tid = threadIdx.x;
    int v = (tid < nb) ? bsum[tid] : 0;
    sh[tid] = v;
    __syncthreads();
    for (int d = 1; d < 1024; d <<= 1) {
        int t = 0;
        if (tid >= d) t = sh[tid - d];
        __syncthreads();
        if (tid >= d) sh[tid] += t;
        __syncthreads();
    }
    if (tid < nb) bsum[tid] = sh[tid] - v;   // exclusive
}
__global__ void k_scan_add(int* __restrict__ off, int n, const int* __restrict__ bsum) {
    int i = blockIdx.x * 1024 + threadIdx.x;
    if (i < n) off[i + 1] += bsum[blockIdx.x];
    if (i == 0) off[0] = 0;
}
__global__ void k_copy_i(int* __restrict__ dst, const int* __restrict__ src, int n) {
    int i = blockIdx.x * blockDim.x + threadIdx.x;
    if (i < n) dst[i] = src[i];
}
__global__ void k_fill(const int* __restrict__ src, const int* __restrict__ dst, int E,
                       int* __restrict__ cursor, int* __restrict__ edges) {
    int e = blockIdx.x * blockDim.x + threadIdx.x;
    if (e < E) {
        int d = dst[e];
        int p = atomicAdd(&cursor[d], 1);
        edges[p] = src[e];
    }
}

// ---------------- CSR gather aggregation: warp per destination row ----------------
__global__ void k_gather(const float4* __restrict__ x, const int* __restrict__ edges,
                         const int* __restrict__ off, float4* __restrict__ out,
                         int n_dst, int domean) {
    int w = (blockIdx.x * blockDim.x + threadIdx.x) >> 5;
    int lane = threadIdx.x & 31;
    if (w >= n_dst) return;
    int beg = off[w], end = off[w + 1];
    float4 acc = make_float4(0.f, 0.f, 0.f, 0.f);
    for (int e = beg; e < end; e++) {
        int s = edges[e];
        float4 v = __ldg(&x[(size_t)s * 32 + lane]);
        acc.x += v.x; acc.y += v.y; acc.z += v.z; acc.w += v.w;
    }
    if (domean) {
        int c = end - beg; if (c < 1) c = 1;
        float inv = 1.0f / (float)c;
        acc.x *= inv; acc.y *= inv; acc.z *= inv; acc.w *= inv;
    }
    out[(size_t)w * 32 + lane] = acc;
}

// ---------------- fused multi-A SGEMM: C = scale*(sum_a A_a @ W_a^T + b0 + b1) ----------------
// mode==1: apply ELU and accumulate per-column sum/sumsq for BN (item path)
__global__ __launch_bounds__(256) void k_gemm(
    const float* __restrict__ A0, const float* __restrict__ A1, const float* __restrict__ A2,
    const float* __restrict__ W0, const float* __restrict__ W1, const float* __restrict__ W2,
    const float* __restrict__ b0, const float* __restrict__ b1,
    float scale, int mode, int NA, int M,
    float* __restrict__ C, float* __restrict__ colsum, float* __restrict__ colsq) {
    __shared__ float As[8][128];
    __shared__ float Bs[8][128];
    const int tid = threadIdx.x;
    const int m0 = blockIdx.x * 128;
    const int lrow = tid >> 1;          // 0..127
    const int lkq = (tid & 1) * 4;      // 0 or 4
    const int tm0 = (tid >> 4) * 8;     // 0..120
    const int tn0 = (tid & 15) * 8;     // 0..120

    float acc[8][8];
#pragma unroll
    for (int i = 0; i < 8; i++)
#pragma unroll
        for (int j = 0; j < 8; j++) acc[i][j] = 0.f;

    const float* Aarr[3] = {A0, A1, A2};
    const float* Warr[3] = {W0, W1, W2};

    for (int a = 0; a < NA; a++) {
        const float* A = Aarr[a];
        const float* W = Warr[a];
        for (int k0 = 0; k0 < 128; k0 += 8) {
            float4 av = make_float4(0.f, 0.f, 0.f, 0.f);
            int gr = m0 + lrow;
            if (gr < M) av = *(const float4*)(A + (size_t)gr * D + k0 + lkq);
            float4 wv = *(const float4*)(W + (size_t)lrow * D + k0 + lkq);
            __syncthreads();
            As[lkq + 0][lrow] = av.x; As[lkq + 1][lrow] = av.y;
            As[lkq + 2][lrow] = av.z; As[lkq + 3][lrow] = av.w;
            Bs[lkq + 0][lrow] = wv.x; Bs[lkq + 1][lrow] = wv.y;
            Bs[lkq + 2][lrow] = wv.z; Bs[lkq + 3][lrow] = wv.w;
            __syncthreads();
#pragma unroll
            for (int kk = 0; kk < 8; kk++) {
                float ar[8], br[8];
                *(float4*)&ar[0] = *(const float4*)&As[kk][tm0];
                *(float4*)&ar[4] = *(const float4*)&As[kk][tm0 + 4];
                *(float4*)&br[0] = *(const float4*)&Bs[kk][tn0];
                *(float4*)&br[4] = *(const float4*)&Bs[kk][tn0 + 4];
#pragma unroll
                for (int i = 0; i < 8; i++)
#pragma unroll
                    for (int j = 0; j < 8; j++)
                        acc[i][j] = fmaf(ar[i], br[j], acc[i][j]);
            }
        }
    }

    __syncthreads();
    float* ssum = &As[0][0];
    float* ssq = &Bs[0][0];
    if (mode == 1) {
        if (tid < 128) { ssum[tid] = 0.f; ssq[tid] = 0.f; }
        __syncthreads();
    }

    float bb[8];
#pragma unroll
    for (int j = 0; j < 8; j++)
        bb[j] = b0[tn0 + j] + (b1 ? b1[tn0 + j] : 0.f);

    float ps[8], pq[8];
#pragma unroll
    for (int j = 0; j < 8; j++) { ps[j] = 0.f; pq[j] = 0.f; }

#pragma unroll
    for (int i = 0; i < 8; i++) {
        int gr = m0 + tm0 + i;
        if (gr >= M) continue;
        float o[8];
#pragma unroll
        for (int j = 0; j < 8; j++) {
            float v = scale * (acc[i][j] + bb[j]);
            if (mode == 1) {
                v = (v > 0.f) ? v : expm1f(v);
                ps[j] += v; pq[j] += v * v;
            }
            o[j] = v;
        }
        *(float4*)(C + (size_t)gr * D + tn0) = *(float4*)&o[0];
        *(float4*)(C + (size_t)gr * D + tn0 + 4) = *(float4*)&o[4];
    }

    if (mode == 1) {
#pragma unroll
        for (int j = 0; j < 8; j++) {
            atomicAdd(&ssum[tn0 + j], ps[j]);
            atomicAdd(&ssq[tn0 + j], pq[j]);
        }
        __syncthreads();
        if (tid < 128) {
            atomicAdd(&colsum[tid], ssum[tid]);
            atomicAdd(&colsq[tid], ssq[tid]);
        }
    }
}

// ---------------- batchnorm ----------------
__global__ void k_bn_prep(const float* __restrict__ stats, const float* __restrict__ g,
                          const float* __restrict__ b, float invN, float* __restrict__ ac) {
    int t = threadIdx.x;  // 128
    float m = stats[t] * invN;
    float var = stats[128 + t] * invN - m * m;
    float r = rsqrtf(var + 1e-5f);
    float a = g[t] * r;
    ac[t] = a;
    ac[128 + t] = b[t] - m * a;
}
__global__ void k_bn_apply(float4* __restrict__ x, int n4, const float* __restrict__ ac) {
    __shared__ float sa[128], sc[128];
    if (threadIdx.x < 128) { sa[threadIdx.x] = ac[threadIdx.x]; sc[threadIdx.x] = ac[128 + threadIdx.x]; }
    __syncthreads();
    int stride = gridDim.x * blockDim.x;
    for (int i = blockIdx.x * blockDim.x + threadIdx.x; i < n4; i += stride) {
        float4 v = x[i];
        int c = (i & 31) * 4;
        v.x = v.x * sa[c + 0] + sc[c + 0];
        v.y = v.y * sa[c + 1] + sc[c + 1];
        v.z = v.z * sa[c + 2] + sc[c + 2];
        v.w = v.w * sa[c + 3] + sc[c + 3];
        x[i] = v;
    }
}

// ---------------- host side ----------------
static void* sym_addr(const void* sym) {
    void* p = nullptr;
    cudaGetSymbolAddress(&p, sym);
    return p;
}

static void build_csr(const int* src, const int* dst, int E, int n,
                      int* off, int* edges, int* cursor, int* bsum) {
    k_zero_i<<<(n + 255) / 256, 256>>>(cursor, n);
    k_count<<<(E + 255) / 256, 256>>>(dst, E, cursor);
    int nb = (n + 1023) / 1024;
    k_scan_block<<<nb, 1024>>>(cursor, n, off, bsum);
    k_scan_bsum<<<1, 1024>>>(bsum, nb);
    k_scan_add<<<nb, 1024>>>(off, n, bsum);
    k_copy_i<<<(n + 255) / 256, 256>>>(cursor, off, n);
    k_fill<<<(E + 255) / 256, 256>>>(src, dst, E, cursor, edges);
}

extern "C" void kernel_launch(void* const* d_in, const int* in_sizes, int n_in,
                              void* d_out, int out_size) {
    const float* x_student = (const float*)d_in[0];
    const float* x_item    = (const float*)d_in[1];
    const float* Wl_ri = (const float*)d_in[2];
    const float* bl_ri = (const float*)d_in[3];
    const float* Wr_ri = (const float*)d_in[4];
    const float* Wl_rs = (const float*)d_in[5];
    const float* bl_rs = (const float*)d_in[6];
    const float* Wr_rs = (const float*)d_in[7];
    const float* W_p   = (const float*)d_in[8];
    const float* b_p   = (const float*)d_in[9];
    const float* bn_g  = (const float*)d_in[10];
    const float* bn_b  = (const float*)d_in[11];
    const int* resp_src = (const int*)d_in[12];
    const int* resp_dst = (const int*)d_in[13];
    const int* rev_src  = (const int*)d_in[14];
    const int* rev_dst  = (const int*)d_in[15];
    const int* prec_src = (const int*)d_in[16];
    const int* prec_dst = (const int*)d_in[17];

    const int NS = in_sizes[0] / D;
    const int NI = in_sizes[1] / D;
    const int E_resp = in_sizes[12];
    const int E_rev  = in_sizes[14];
    const int E_prec = in_sizes[16];

    float* aggI = (float*)sym_addr(g_aggI);
    float* aggS = (float*)sym_addr(g_aggS);
    float* aggP = (float*)sym_addr(g_aggP);
    int* off_resp  = (int*)sym_addr(g_off_resp);
    int* edge_resp = (int*)sym_addr(g_edge_resp);
    int* off_rev   = (int*)sym_addr(g_off_rev);
    int* edge_rev  = (int*)sym_addr(g_edge_rev);
    int* off_prec  = (int*)sym_addr(g_off_prec);
    int* edge_prec = (int*)sym_addr(g_edge_prec);
    int* cursor = (int*)sym_addr(g_cursor);
    int* bsum   = (int*)sym_addr(g_bsum);
    float* colstats = (float*)sym_addr(g_colstats);
    float* bn_ac    = (float*)sym_addr(g_bn_ac);

    float* xi_out = (float*)d_out;                 // NI x D
    float* xs_out = xi_out + (size_t)NI * D;       // NS x D

    // CSR graphs (depend only on inputs; rebuilt every call)
    build_csr(resp_src, resp_dst, E_resp, NI, off_resp, edge_resp, cursor, bsum);
    build_csr(rev_src, rev_dst, E_rev, NS, off_rev, edge_rev, cursor, bsum);
    build_csr(prec_src, prec_dst, E_prec, NS, off_prec, edge_prec, cursor, bsum);

    const float* xs_cur = x_student;
    const float* xi_cur = x_item;

    const int gtI = (NI + 7) / 8;   // gather: 8 warps / block
    const int gtS = (NS + 7) / 8;
    const int gbI = (NI + 127) / 128;
    const int gbS = (NS + 127) / 128;

    for (int l = 0; l < 2; l++) {
        const size_t wOff = (size_t)l * D * D;
        const size_t bOff = (size_t)l * D;

        // aggregations (read old xs/xi)
        k_gather<<<gtI, 256>>>((const float4*)xs_cur, edge_resp, off_resp,
                               (float4*)aggI, NI, 1);
        k_gather<<<gtS, 256>>>((const float4*)xi_cur, edge_rev, off_rev,
                               (float4*)aggS, NS, 1);
        k_gather<<<gtS, 256>>>((const float4*)xs_cur, edge_prec, off_prec,
                               (float4*)aggP, NS, 0);

        // item path: fused GEMM (K=256) + bias + ELU + BN stats
        k_zero_f<<<1, 256>>>(colstats, 256);
        k_gemm<<<gbI, 256>>>(aggI, xi_cur, nullptr,
                             Wl_ri + wOff, Wr_ri + wOff, nullptr,
                             bl_ri + bOff, nullptr,
                             1.0f, 1, 2, NI, xi_out,
                             colstats, colstats + 128);
        k_bn_prep<<<1, 128>>>(colstats, bn_g + bOff, bn_b + bOff,
                              1.0f / (float)NI, bn_ac);
        k_bn_apply<<<512, 256>>>((float4*)xi_out, NI * 32, bn_ac);

        // student path: fused GEMM (K=384), out = 0.5*(sum + bl_rs + b_p)
        k_gemm<<<gbS, 256>>>(aggS, xs_cur, aggP,
                             Wl_rs + wOff, Wr_rs + wOff, W_p + wOff,
                             bl_rs + bOff, b_p + bOff,
                             0.5f, 0, 3, NS, xs_out,
                             nullptr, nullptr);

        xs_cur = xs_out;
        xi_cur = xi_out;
    }
}

// round 4
// speedup vs baseline: 1.6594x; 1.6594x over previous
#include <cuda_runtime.h>
#include <math.h>
#include <stdint.h>

#define D 128
#define NS_MAX 100000
#define NI_MAX 20000
#define E_MAX  600000

// ---------------- device scratch (static, no allocation) ----------------
__device__ float g_aggI[(size_t)NI_MAX * D];
__device__ float g_aggS[(size_t)NS_MAX * D];
__device__ float g_aggP[(size_t)NS_MAX * D];

__device__ int g_off_resp[NI_MAX + 1];
__device__ int g_edge_resp[E_MAX];
__device__ int g_off_rev[NS_MAX + 1];
__device__ int g_edge_rev[E_MAX];
__device__ int g_off_prec[NS_MAX + 1];
__device__ int g_edge_prec[E_MAX];

__device__ int   g_cursor[NS_MAX + 1];
__device__ int   g_bsum[1024];
__device__ float g_colstats[256];   // [0:128) sum, [128:256) sumsq
__device__ float g_bn_ac[256];      // [0:128) a,   [128:256) c

// ---------------- small utility kernels ----------------
__global__ void k_zero_i(int* __restrict__ p, int n) {
    int i = blockIdx.x * blockDim.x + threadIdx.x;
    if (i < n) p[i] = 0;
}
__global__ void k_zero_f(float* __restrict__ p, int n) {
    int i = blockIdx.x * blockDim.x + threadIdx.x;
    if (i < n) p[i] = 0.f;
}
__global__ void k_count(const int* __restrict__ dst, int E, int* __restrict__ cnt) {
    int i = blockIdx.x * blockDim.x + threadIdx.x;
    if (i < E) atomicAdd(&cnt[dst[i]], 1);
}
// block-level inclusive scan; writes off[i+1], block totals to bsum
__global__ void k_scan_block(const int* __restrict__ cnt, int n,
                             int* __restrict__ off, int* __restrict__ bsum) {
    __shared__ int sh[1024];
    int tid = threadIdx.x;
    int i = blockIdx.x * 1024 + tid;
    int v = (i < n) ? cnt[i] : 0;
    sh[tid] = v;
    __syncthreads();
    for (int d = 1; d < 1024; d <<= 1) {
        int t = 0;
        if (tid >= d) t = sh[tid - d];
        __syncthreads();
        if (tid >= d) sh[tid] += t;
        __syncthreads();
    }
    if (i < n) off[i + 1] = sh[tid];
    if (tid == 1023) bsum[blockIdx.x] = sh[1023];
}
// single-block exclusive scan of block sums (nb <= 1024)
__global__ void k_scan_bsum(int* __restrict__ bsum, int nb) {
    __shared__ int sh[1024];
    int tid = threadIdx.x;
    int v = (tid < nb) ? bsum[tid] : 0;
    sh[tid] = v;
    __syncthreads();
    for (int d = 1; d < 1024; d <<= 1) {
        int t = 0;
        if (tid >= d) t = sh[tid - d];
        __syncthreads();
        if (tid >= d) sh[tid] += t;
        __syncthreads();
    }
    if (tid < nb) bsum[tid] = sh[tid] - v;   // exclusive
}
__global__ void k_scan_add(int* __restrict__ off, int n, const int* __restrict__ bsum) {
    int i = blockIdx.x * 1024 + threadIdx.x;
    if (i < n) off[i + 1] += bsum[blockIdx.x];
    if (i == 0) off[0] = 0;
}
__global__ void k_copy_i(int* __restrict__ dst, const int* __restrict__ src, int n) {
    int i = blockIdx.x * blockDim.x + threadIdx.x;
    if (i < n) dst[i] = src[i];
}
__global__ void k_fill(const int* __restrict__ src, const int* __restrict__ dst, int E,
                       int* __restrict__ cursor, int* __restrict__ edges) {
    int e = blockIdx.x * blockDim.x + threadIdx.x;
    if (e < E) {
        int d = dst[e];
        int p = atomicAdd(&cursor[d], 1);
        edges[p] = src[e];
    }
}

// ---------------- CSR gather aggregation: warp per destination row ----------------
__global__ void k_gather(const float4* __restrict__ x, const int* __restrict__ edges,
                         const int* __restrict__ off, float4* __restrict__ out,
                         int n_dst, int domean) {
    int w = (blockIdx.x * blockDim.x + threadIdx.x) >> 5;
    int lane = threadIdx.x & 31;
    if (w >= n_dst) return;
    int beg = off[w], end = off[w + 1];
    float4 acc = make_float4(0.f, 0.f, 0.f, 0.f);
    for (int e = beg; e < end; e++) {
        int s = edges[e];
        float4 v = __ldg(&x[(size_t)s * 32 + lane]);
        acc.x += v.x; acc.y += v.y; acc.z += v.z; acc.w += v.w;
    }
    if (domean) {
        int c = end - beg; if (c < 1) c = 1;
        float inv = 1.0f / (float)c;
        acc.x *= inv; acc.y *= inv; acc.z *= inv; acc.w *= inv;
    }
    out[(size_t)w * 32 + lane] = acc;
}

// ---------------- TF32 tensor-core GEMM ----------------
// C = scale * (sum_a A_a @ W_a^T + b0 + b1)
// mode==1: ELU + per-column sum/sumsq accumulation (item path, BN stats)
// Tiles: BM=128, BN=128(=D), BK=16. 8 warps (4x2), warp tile 32x64.
// SMEM rows stride 20 floats -> conflict-free fragment loads.

#define BK  16
#define LDT 20

__device__ __forceinline__ uint32_t f2tf32(float f) {
    uint32_t r;
    asm("cvt.rna.tf32.f32 %0, %1;" : "=r"(r) : "f"(f));
    return r;
}

__device__ __forceinline__ void mma_tf32(float c[4],
                                         uint32_t a0, uint32_t a1, uint32_t a2, uint32_t a3,
                                         uint32_t b0, uint32_t b1) {
    asm volatile(
        "mma.sync.aligned.m16n8k8.row.col.f32.tf32.tf32.f32 "
        "{%0,%1,%2,%3}, {%4,%5,%6,%7}, {%8,%9}, {%0,%1,%2,%3};"
        : "+f"(c[0]), "+f"(c[1]), "+f"(c[2]), "+f"(c[3])
        : "r"(a0), "r"(a1), "r"(a2), "r"(a3), "r"(b0), "r"(b1));
}

__global__ __launch_bounds__(256, 2) void k_gemm_tc(
    const float* __restrict__ A0, const float* __restrict__ A1, const float* __restrict__ A2,
    const float* __restrict__ W0, const float* __restrict__ W1, const float* __restrict__ W2,
    const float* __restrict__ b0, const float* __restrict__ b1,
    float scale, int mode, int NA, int M,
    float* __restrict__ C, float* __restrict__ colsum, float* __restrict__ colsq) {

    __shared__ uint32_t sA[2][128 * LDT];
    __shared__ uint32_t sB[2][128 * LDT];
    __shared__ float ssum[128], ssq[128];

    const int tid  = threadIdx.x;
    const int m0   = blockIdx.x * 128;
    const int warp = tid >> 5;
    const int lane = tid & 31;
    const int wm   = warp >> 1;      // 0..3
    const int wn   = warp & 1;       // 0..1
    const int g    = lane >> 2;      // 0..7
    const int t4   = lane & 3;       // 0..3

    // global<->smem tile mapping: 512 float4 per tile, 2 per thread
    const int r0  = tid >> 2;            // 0..63
    const int r1  = r0 + 64;             // 64..127
    const int cq  = (tid & 3) * 4;       // 0,4,8,12

    const float* Aarr[3] = {A0, A1, A2};
    const float* Warr[3] = {W0, W1, W2};

    float acc[2][8][4];
#pragma unroll
    for (int i = 0; i < 2; i++)
#pragma unroll
        for (int j = 0; j < 8; j++)
#pragma unroll
            for (int c = 0; c < 4; c++) acc[i][j][c] = 0.f;

    const int KT = NA * (D / BK);

    float4 av0, av1, bv0, bv1;
    // prologue: load tile 0
    {
        const float* A = Aarr[0];
        const float* W = Warr[0];
        const float4 z = make_float4(0.f, 0.f, 0.f, 0.f);
        int gr0 = m0 + r0, gr1 = m0 + r1;
        av0 = (gr0 < M) ? *(const float4*)(A + (size_t)gr0 * D + cq) : z;
        av1 = (gr1 < M) ? *(const float4*)(A + (size_t)gr1 * D + cq) : z;
        bv0 = *(const float4*)(W + (size_t)r0 * D + cq);
        bv1 = *(const float4*)(W + (size_t)r1 * D + cq);
    }

    int buf = 0;
    for (int t = 0; t < KT; t++) {
        // store prefetched tile (convert to tf32)
        {
            uint4 u;
            u.x = f2tf32(av0.x); u.y = f2tf32(av0.y); u.z = f2tf32(av0.z); u.w = f2tf32(av0.w);
            *(uint4*)&sA[buf][r0 * LDT + cq] = u;
            u.x = f2tf32(av1.x); u.y = f2tf32(av1.y); u.z = f2tf32(av1.z); u.w = f2tf32(av1.w);
            *(uint4*)&sA[buf][r1 * LDT + cq] = u;
            u.x = f2tf32(bv0.x); u.y = f2tf32(bv0.y); u.z = f2tf32(bv0.z); u.w = f2tf32(bv0.w);
            *(uint4*)&sB[buf][r0 * LDT + cq] = u;
            u.x = f2tf32(bv1.x); u.y = f2tf32(bv1.y); u.z = f2tf32(bv1.z); u.w = f2tf32(bv1.w);
            *(uint4*)&sB[buf][r1 * LDT + cq] = u;
        }
        __syncthreads();

        // prefetch next tile
        if (t + 1 < KT) {
            int tn = t + 1;
            int a  = tn >> 3;               // D/BK = 8 tiles per matrix
            int k0 = (tn & 7) * BK;
            const float* A = Aarr[a];
            const float* W = Warr[a];
            const float4 z = make_float4(0.f, 0.f, 0.f, 0.f);
            int gr0 = m0 + r0, gr1 = m0 + r1;
            av0 = (gr0 < M) ? *(const float4*)(A + (size_t)gr0 * D + k0 + cq) : z;
            av1 = (gr1 < M) ? *(const float4*)(A + (size_t)gr1 * D + k0 + cq) : z;
            bv0 = *(const float4*)(W + (size_t)r0 * D + k0 + cq);
            bv1 = *(const float4*)(W + (size_t)r1 * D + k0 + cq);
        }

        // compute on current buffer: BK=16 -> two k8 steps
        const uint32_t* cA = sA[buf];
        const uint32_t* cB = sB[buf];
#pragma unroll
        for (int kk = 0; kk < BK; kk += 8) {
            uint32_t af[2][4];
#pragma unroll
            for (int i = 0; i < 2; i++) {
                int mb = wm * 32 + i * 16;
                af[i][0] = cA[(mb + g)     * LDT + kk + t4];
                af[i][1] = cA[(mb + g + 8) * LDT + kk + t4];
                af[i][2] = cA[(mb + g)     * LDT + kk + t4 + 4];
                af[i][3] = cA[(mb + g + 8) * LDT + kk + t4 + 4];
            }
#pragma unroll
            for (int j = 0; j < 8; j++) {
                int nb = wn * 64 + j * 8;
                uint32_t bf0 = cB[(nb + g) * LDT + kk + t4];
                uint32_t bf1 = cB[(nb + g) * LDT + kk + t4 + 4];
                mma_tf32(acc[0][j], af[0][0], af[0][1], af[0][2], af[0][3], bf0, bf1);
                mma_tf32(acc[1][j], af[1][0], af[1][1], af[1][2], af[1][3], bf0, bf1);
            }
        }
        buf ^= 1;
        __syncthreads();
    }

    // ---------------- epilogue ----------------
    if (mode == 1) {
        if (tid < 128) { ssum[tid] = 0.f; ssq[tid] = 0.f; }
        __syncthreads();
    }

    float2 bias[8];
#pragma unroll
    for (int j = 0; j < 8; j++) {
        int col = wn * 64 + j * 8 + t4 * 2;
        bias[j].x = b0[col]     + (b1 ? b1[col]     : 0.f);
        bias[j].y = b0[col + 1] + (b1 ? b1[col + 1] : 0.f);
    }

    float ps[16], pq[16];
#pragma unroll
    for (int j = 0; j < 16; j++) { ps[j] = 0.f; pq[j] = 0.f; }

#pragma unroll
    for (int i = 0; i < 2; i++) {
        int row0 = m0 + wm * 32 + i * 16 + g;
        int row1 = row0 + 8;
#pragma unroll
        for (int j = 0; j < 8; j++) {
            int col = wn * 64 + j * 8 + t4 * 2;
            if (row0 < M) {
                float v0 = scale * (acc[i][j][0] + bias[j].x);
                float v1 = scale * (acc[i][j][1] + bias[j].y);
                if (mode == 1) {
                    v0 = (v0 > 0.f) ? v0 : expm1f(v0);
                    v1 = (v1 > 0.f) ? v1 : expm1f(v1);
                    ps[j * 2] += v0; pq[j * 2] += v0 * v0;
                    ps[j * 2 + 1] += v1; pq[j * 2 + 1] += v1 * v1;
                }
                *(float2*)(C + (size_t)row0 * D + col) = make_float2(v0, v1);
            }
            if (row1 < M) {
                float v0 = scale * (acc[i][j][2] + bias[j].x);
                float v1 = scale * (acc[i][j][3] + bias[j].y);
                if (mode == 1) {
                    v0 = (v0 > 0.f) ? v0 : expm1f(v0);
                    v1 = (v1 > 0.f) ? v1 : expm1f(v1);
                    ps[j * 2] += v0; pq[j * 2] += v0 * v0;
                    ps[j * 2 + 1] += v1; pq[j * 2 + 1] += v1 * v1;
                }
                *(float2*)(C + (size_t)row1 * D + col) = make_float2(v0, v1);
            }
        }
    }

    if (mode == 1) {
#pragma unroll
        for (int j = 0; j < 8; j++) {
            int col = wn * 64 + j * 8 + t4 * 2;
            atomicAdd(&ssum[col], ps[j * 2]);
            atomicAdd(&ssq[col], pq[j * 2]);
            atomicAdd(&ssum[col + 1], ps[j * 2 + 1]);
            atomicAdd(&ssq[col + 1], pq[j * 2 + 1]);
        }
        __syncthreads();
        if (tid < 128) {
            atomicAdd(&colsum[tid], ssum[tid]);
            atomicAdd(&colsq[tid], ssq[tid]);
        }
    }
}

// ---------------- batchnorm ----------------
__global__ void k_bn_prep(const float* __restrict__ stats, const float* __restrict__ g,
                          const float* __restrict__ b, float invN, float* __restrict__ ac) {
    int t = threadIdx.x;  // 128
    float m = stats[t] * invN;
    float var = stats[128 + t] * invN - m * m;
    float r = rsqrtf(var + 1e-5f);
    float a = g[t] * r;
    ac[t] = a;
    ac[128 + t] = b[t] - m * a;
}
__global__ void k_bn_apply(float4* __restrict__ x, int n4, const float* __restrict__ ac) {
    __shared__ float sa[128], sc[128];
    if (threadIdx.x < 128) { sa[threadIdx.x] = ac[threadIdx.x]; sc[threadIdx.x] = ac[128 + threadIdx.x]; }
    __syncthreads();
    int stride = gridDim.x * blockDim.x;
    for (int i = blockIdx.x * blockDim.x + threadIdx.x; i < n4; i += stride) {
        float4 v = x[i];
        int c = (i & 31) * 4;
        v.x = v.x * sa[c + 0] + sc[c + 0];
        v.y = v.y * sa[c + 1] + sc[c + 1];
        v.z = v.z * sa[c + 2] + sc[c + 2];
        v.w = v.w * sa[c + 3] + sc[c + 3];
        x[i] = v;
    }
}

// ---------------- host side ----------------
static void* sym_addr(const void* sym) {
    void* p = nullptr;
    cudaGetSymbolAddress(&p, sym);
    return p;
}

static void build_csr(const int* src, const int* dst, int E, int n,
                      int* off, int* edges, int* cursor, int* bsum) {
    k_zero_i<<<(n + 255) / 256, 256>>>(cursor, n);
    k_count<<<(E + 255) / 256, 256>>>(dst, E, cursor);
    int nb = (n + 1023) / 1024;
    k_scan_block<<<nb, 1024>>>(cursor, n, off, bsum);
    k_scan_bsum<<<1, 1024>>>(bsum, nb);
    k_scan_add<<<nb, 1024>>>(off, n, bsum);
    k_copy_i<<<(n + 255) / 256, 256>>>(cursor, off, n);
    k_fill<<<(E + 255) / 256, 256>>>(src, dst, E, cursor, edges);
}

extern "C" void kernel_launch(void* const* d_in, const int* in_sizes, int n_in,
                              void* d_out, int out_size) {
    const float* x_student = (const float*)d_in[0];
    const float* x_item    = (const float*)d_in[1];
    const float* Wl_ri = (const float*)d_in[2];
    const float* bl_ri = (const float*)d_in[3];
    const float* Wr_ri = (const float*)d_in[4];
    const float* Wl_rs = (const float*)d_in[5];
    const float* bl_rs = (const float*)d_in[6];
    const float* Wr_rs = (const float*)d_in[7];
    const float* W_p   = (const float*)d_in[8];
    const float* b_p   = (const float*)d_in[9];
    const float* bn_g  = (const float*)d_in[10];
    const float* bn_b  = (const float*)d_in[11];
    const int* resp_src = (const int*)d_in[12];
    const int* resp_dst = (const int*)d_in[13];
    const int* rev_src  = (const int*)d_in[14];
    const int* rev_dst  = (const int*)d_in[15];
    const int* prec_src = (const int*)d_in[16];
    const int* prec_dst = (const int*)d_in[17];

    const int NS = in_sizes[0] / D;
    const int NI = in_sizes[1] / D;
    const int E_resp = in_sizes[12];
    const int E_rev  = in_sizes[14];
    const int E_prec = in_sizes[16];

    float* aggI = (float*)sym_addr(g_aggI);
    float* aggS = (float*)sym_addr(g_aggS);
    float* aggP = (float*)sym_addr(g_aggP);
    int* off_resp  = (int*)sym_addr(g_off_resp);
    int* edge_resp = (int*)sym_addr(g_edge_resp);
    int* off_rev   = (int*)sym_addr(g_off_rev);
    int* edge_rev  = (int*)sym_addr(g_edge_rev);
    int* off_prec  = (int*)sym_addr(g_off_prec);
    int* edge_prec = (int*)sym_addr(g_edge_prec);
    int* cursor = (int*)sym_addr(g_cursor);
    int* bsum   = (int*)sym_addr(g_bsum);
    float* colstats = (float*)sym_addr(g_colstats);
    float* bn_ac    = (float*)sym_addr(g_bn_ac);

    float* xi_out = (float*)d_out;                 // NI x D
    float* xs_out = xi_out + (size_t)NI * D;       // NS x D

    // CSR graphs (depend only on inputs; rebuilt every call)
    build_csr(resp_src, resp_dst, E_resp, NI, off_resp, edge_resp, cursor, bsum);
    build_csr(rev_src, rev_dst, E_rev, NS, off_rev, edge_rev, cursor, bsum);
    build_csr(prec_src, prec_dst, E_prec, NS, off_prec, edge_prec, cursor, bsum);

    const float* xs_cur = x_student;
    const float* xi_cur = x_item;

    const int gtI = (NI + 7) / 8;   // gather: 8 warps / block
    const int gtS = (NS + 7) / 8;
    const int gbI = (NI + 127) / 128;
    const int gbS = (NS + 127) / 128;

    for (int l = 0; l < 2; l++) {
        const size_t wOff = (size_t)l * D * D;
        const size_t bOff = (size_t)l * D;

        // aggregations (read old xs/xi)
        k_gather<<<gtI, 256>>>((const float4*)xs_cur, edge_resp, off_resp,
                               (float4*)aggI, NI, 1);
        k_gather<<<gtS, 256>>>((const float4*)xi_cur, edge_rev, off_rev,
                               (float4*)aggS, NS, 1);
        k_gather<<<gtS, 256>>>((const float4*)xs_cur, edge_prec, off_prec,
                               (float4*)aggP, NS, 0);

        // item path: fused TF32 GEMM (K=256) + bias + ELU + BN stats
        k_zero_f<<<1, 256>>>(colstats, 256);
        k_gemm_tc<<<gbI, 256>>>(aggI, xi_cur, nullptr,
                                Wl_ri + wOff, Wr_ri + wOff, nullptr,
                                bl_ri + bOff, nullptr,
                                1.0f, 1, 2, NI, xi_out,
                                colstats, colstats + 128);
        k_bn_prep<<<1, 128>>>(colstats, bn_g + bOff, bn_b + bOff,
                              1.0f / (float)NI, bn_ac);
        k_bn_apply<<<512, 256>>>((float4*)xi_out, NI * 32, bn_ac);

        // student path: fused TF32 GEMM (K=384), out = 0.5*(sum + bl_rs + b_p)
        k_gemm_tc<<<gbS, 256>>>(aggS, xs_cur, aggP,
                                Wl_rs + wOff, Wr_rs + wOff, W_p + wOff,
                                bl_rs + bOff, b_p + bOff,
                                0.5f, 0, 3, NS, xs_out,
                                nullptr, nullptr);

        xs_cur = xs_out;
        xi_cur = xi_out;
    }
}

// round 5
// speedup vs baseline: 1.6706x; 1.0067x over previous
#include <cuda_runtime.h>
#include <math.h>
#include <stdint.h>

#define D 128
#define NS_MAX 100000
#define NI_MAX 20000
#define E_MAX  600000

// ---------------- device scratch (static, no allocation) ----------------
// agg buffers hold TF32-rounded values (stored as uint32 bit patterns in float arrays)
__device__ float g_aggI[(size_t)NI_MAX * D];
__device__ float g_aggS[(size_t)NS_MAX * D];
__device__ float g_aggP[(size_t)NS_MAX * D];
// TF32 shadows of current xs / xi (A-operands for GEMMs)
__device__ unsigned g_xs32[(size_t)NS_MAX * D];
__device__ unsigned g_xi32[(size_t)NI_MAX * D];
// TF32 shadows of weights: [L*D*D] each
__device__ unsigned g_w_lri[2 * D * D];
__device__ unsigned g_w_rri[2 * D * D];
__device__ unsigned g_w_lrs[2 * D * D];
__device__ unsigned g_w_rrs[2 * D * D];
__device__ unsigned g_w_p[2 * D * D];

__device__ int g_off_resp[NI_MAX + 1];
__device__ int g_edge_resp[E_MAX];
__device__ int g_off_rev[NS_MAX + 1];
__device__ int g_edge_rev[E_MAX];
__device__ int g_off_prec[NS_MAX + 1];
__device__ int g_edge_prec[E_MAX];

__device__ int   g_cursor[NS_MAX + 1];
__device__ int   g_bsum[1024];
__device__ float g_colstats[256];   // [0:128) sum, [128:256) sumsq
__device__ float g_bn_ac[256];      // [0:128) a,   [128:256) c

__device__ __forceinline__ uint32_t f2tf32(float f) {
    uint32_t r;
    asm("cvt.rna.tf32.f32 %0, %1;" : "=r"(r) : "f"(f));
    return r;
}

// ---------------- small utility kernels ----------------
__global__ void k_zero_i(int* __restrict__ p, int n) {
    int i = blockIdx.x * blockDim.x + threadIdx.x;
    if (i < n) p[i] = 0;
}
__global__ void k_zero_f(float* __restrict__ p, int n) {
    int i = blockIdx.x * blockDim.x + threadIdx.x;
    if (i < n) p[i] = 0.f;
}
__global__ void k_cvt(const float4* __restrict__ in, uint4* __restrict__ out, int n4) {
    int i = blockIdx.x * blockDim.x + threadIdx.x;
    if (i < n4) {
        float4 v = in[i];
        uint4 u;
        u.x = f2tf32(v.x); u.y = f2tf32(v.y); u.z = f2tf32(v.z); u.w = f2tf32(v.w);
        out[i] = u;
    }
}
__global__ void k_count(const int* __restrict__ dst, int E, int* __restrict__ cnt) {
    int i = blockIdx.x * blockDim.x + threadIdx.x;
    if (i < E) atomicAdd(&cnt[dst[i]], 1);
}
__global__ void k_scan_block(const int* __restrict__ cnt, int n,
                             int* __restrict__ off, int* __restrict__ bsum) {
    __shared__ int sh[1024];
    int tid = threadIdx.x;
    int i = blockIdx.x * 1024 + tid;
    int v = (i < n) ? cnt[i] : 0;
    sh[tid] = v;
    __syncthreads();
    for (int d = 1; d < 1024; d <<= 1) {
        int t = 0;
        if (tid >= d) t = sh[tid - d];
        __syncthreads();
        if (tid >= d) sh[tid] += t;
        __syncthreads();
    }
    if (i < n) off[i + 1] = sh[tid];
    if (tid == 1023) bsum[blockIdx.x] = sh[1023];
}
__global__ void k_scan_bsum(int* __restrict__ bsum, int nb) {
    __shared__ int sh[1024];
    int tid = threadIdx.x;
    int v = (tid < nb) ? bsum[tid] : 0;
    sh[tid] = v;
    __syncthreads();
    for (int d = 1; d < 1024; d <<= 1) {
        int t = 0;
        if (tid >= d) t = sh[tid - d];
        __syncthreads();
        if (tid >= d) sh[tid] += t;
        __syncthreads();
    }
    if (tid < nb) bsum[tid] = sh[tid] - v;   // exclusive
}
__global__ void k_scan_add(int* __restrict__ off, int n, const int* __restrict__ bsum) {
    int i = blockIdx.x * 1024 + threadIdx.x;
    if (i < n) off[i + 1] += bsum[blockIdx.x];
    if (i == 0) off[0] = 0;
}
__global__ void k_copy_i(int* __restrict__ dst, const int* __restrict__ src, int n) {
    int i = blockIdx.x * blockDim.x + threadIdx.x;
    if (i < n) dst[i] = src[i];
}
__global__ void k_fill(const int* __restrict__ src, const int* __restrict__ dst, int E,
                       int* __restrict__ cursor, int* __restrict__ edges) {
    int e = blockIdx.x * blockDim.x + threadIdx.x;
    if (e < E) {
        int d = dst[e];
        int p = atomicAdd(&cursor[d], 1);
        edges[p] = src[e];
    }
}

// ---------------- CSR gather aggregation: warp per destination row --------------
// fp32 accumulate, TF32-rounded output (GEMM A-operand)
__global__ void k_gather(const float4* __restrict__ x, const int* __restrict__ edges,
                         const int* __restrict__ off, uint4* __restrict__ out,
                         int n_dst, int domean) {
    int w = (blockIdx.x * blockDim.x + threadIdx.x) >> 5;
    int lane = threadIdx.x & 31;
    if (w >= n_dst) return;
    int beg = off[w], end = off[w + 1];
    float4 acc = make_float4(0.f, 0.f, 0.f, 0.f);
    for (int e = beg; e < end; e++) {
        int s = edges[e];
        float4 v = __ldg(&x[(size_t)s * 32 + lane]);
        acc.x += v.x; acc.y += v.y; acc.z += v.z; acc.w += v.w;
    }
    if (domean) {
        int c = end - beg; if (c < 1) c = 1;
        float inv = 1.0f / (float)c;
        acc.x *= inv; acc.y *= inv; acc.z *= inv; acc.w *= inv;
    }
    uint4 o;
    o.x = f2tf32(acc.x); o.y = f2tf32(acc.y); o.z = f2tf32(acc.z); o.w = f2tf32(acc.w);
    out[(size_t)w * 32 + lane] = o;
}

// ---------------- TF32 tensor-core GEMM, cp.async 4-stage pipeline ----------------
// C = scale * (sum_a A_a @ W_a^T + b0 + b1); operands are pre-converted TF32.
// mode==1: ELU + per-column sum/sumsq (BN stats). Cshadow: optional TF32 copy of C.

#define BK   16
#define LDT  20
#define TILE (128 * LDT)

__device__ __forceinline__ void cp16(uint32_t dst, const void* src, int srcsize) {
    asm volatile("cp.async.cg.shared.global [%0], [%1], 16, %2;"
                 :: "r"(dst), "l"(src), "r"(srcsize));
}

__device__ __forceinline__ void mma_tf32(float c[4],
                                         uint32_t a0, uint32_t a1, uint32_t a2, uint32_t a3,
                                         uint32_t b0, uint32_t b1) {
    asm volatile(
        "mma.sync.aligned.m16n8k8.row.col.f32.tf32.tf32.f32 "
        "{%0,%1,%2,%3}, {%4,%5,%6,%7}, {%8,%9}, {%0,%1,%2,%3};"
        : "+f"(c[0]), "+f"(c[1]), "+f"(c[2]), "+f"(c[3])
        : "r"(a0), "r"(a1), "r"(a2), "r"(a3), "r"(b0), "r"(b1));
}

__global__ __launch_bounds__(256, 2) void k_gemm_tc(
    const uint32_t* __restrict__ A0, const uint32_t* __restrict__ A1, const uint32_t* __restrict__ A2,
    const uint32_t* __restrict__ W0, const uint32_t* __restrict__ W1, const uint32_t* __restrict__ W2,
    const float* __restrict__ b0, const float* __restrict__ b1,
    float scale, int mode, int NA, int M,
    float* __restrict__ C, uint32_t* __restrict__ Cshadow,
    float* __restrict__ colsum, float* __restrict__ colsq) {

    extern __shared__ uint32_t smemu[];
    uint32_t* sA = smemu;            // 4 stages * TILE
    uint32_t* sB = smemu + 4 * TILE; // 4 stages * TILE
    __shared__ float ssum[128], ssq[128];

    const int tid  = threadIdx.x;
    const int m0   = blockIdx.x * 128;
    const int warp = tid >> 5;
    const int lane = tid & 31;
    const int wm   = warp >> 1;      // 0..3
    const int wn   = warp & 1;       // 0..1
    const int g    = lane >> 2;      // 0..7
    const int t4   = lane & 3;       // 0..3

    // tile load mapping: 512 x 16B per matrix per stage, 2 per thread
    const int r0  = tid >> 2;            // 0..63
    const int r1  = r0 + 64;             // 64..127
    const int cq  = (tid & 3) * 4;       // 0,4,8,12

    const int gr0 = m0 + r0, gr1 = m0 + r1;
    const int szA0 = (gr0 < M) ? 16 : 0;
    const int szA1 = (gr1 < M) ? 16 : 0;

    const uint32_t* Aarr[3] = {A0, A1, A2};
    const uint32_t* Warr[3] = {W0, W1, W2};

    const uint32_t sA_addr = (uint32_t)__cvta_generic_to_shared(sA);
    const uint32_t sB_addr = (uint32_t)__cvta_generic_to_shared(sB);
    const uint32_t dOffA = (r0 * LDT + cq) * 4;
    const uint32_t dOffStep = 64 * LDT * 4;

    float acc[2][8][4];
#pragma unroll
    for (int i = 0; i < 2; i++)
#pragma unroll
        for (int j = 0; j < 8; j++)
#pragma unroll
            for (int c = 0; c < 4; c++) acc[i][j][c] = 0.f;

    const int KT = NA * (D / BK);

    auto issue = [&](int t, int st) {
        int a  = t >> 3;
        int k0 = (t & 7) * BK;
        const uint32_t* A = Aarr[a];
        const uint32_t* W = Warr[a];
        uint32_t dA = sA_addr + st * (TILE * 4) + dOffA;
        uint32_t dB = sB_addr + st * (TILE * 4) + dOffA;
        cp16(dA,            A + (size_t)gr0 * D + k0 + cq, szA0);
        cp16(dA + dOffStep, A + (size_t)gr1 * D + k0 + cq, szA1);
        cp16(dB,            W + (size_t)r0 * D + k0 + cq, 16);
        cp16(dB + dOffStep, W + (size_t)r1 * D + k0 + cq, 16);
    };

    // prologue: 3 stages in flight
#pragma unroll
    for (int s = 0; s < 3; s++) {
        issue(s, s);
        asm volatile("cp.async.commit_group;");
    }

    for (int t = 0; t < KT; t++) {
        asm volatile("cp.async.wait_group 2;");
        __syncthreads();

        if (t + 3 < KT) issue(t + 3, (t + 3) & 3);
        asm volatile("cp.async.commit_group;");

        const uint32_t* cA = sA + (t & 3) * TILE;
        const uint32_t* cB = sB + (t & 3) * TILE;
#pragma unroll
        for (int kk = 0; kk < BK; kk += 8) {
            uint32_t af[2][4];
#pragma unroll
            for (int i = 0; i < 2; i++) {
                int mb = wm * 32 + i * 16;
                af[i][0] = cA[(mb + g)     * LDT + kk + t4];
                af[i][1] = cA[(mb + g + 8) * LDT + kk + t4];
                af[i][2] = cA[(mb + g)     * LDT + kk + t4 + 4];
                af[i][3] = cA[(mb + g + 8) * LDT + kk + t4 + 4];
            }
#pragma unroll
            for (int j = 0; j < 8; j++) {
                int nb = wn * 64 + j * 8;
                uint32_t bf0 = cB[(nb + g) * LDT + kk + t4];
                uint32_t bf1 = cB[(nb + g) * LDT + kk + t4 + 4];
                mma_tf32(acc[0][j], af[0][0], af[0][1], af[0][2], af[0][3], bf0, bf1);
                mma_tf32(acc[1][j], af[1][0], af[1][1], af[1][2], af[1][3], bf0, bf1);
            }
        }
        __syncthreads();
    }

    // ---------------- epilogue ----------------
    if (mode == 1) {
        if (tid < 128) { ssum[tid] = 0.f; ssq[tid] = 0.f; }
        __syncthreads();
    }

    float2 bias[8];
#pragma unroll
    for (int j = 0; j < 8; j++) {
        int col = wn * 64 + j * 8 + t4 * 2;
        bias[j].x = b0[col]     + (b1 ? b1[col]     : 0.f);
        bias[j].y = b0[col + 1] + (b1 ? b1[col + 1] : 0.f);
    }

    float ps[16], pq[16];
#pragma unroll
    for (int j = 0; j < 16; j++) { ps[j] = 0.f; pq[j] = 0.f; }

#pragma unroll
    for (int i = 0; i < 2; i++) {
        int row0 = m0 + wm * 32 + i * 16 + g;
        int row1 = row0 + 8;
#pragma unroll
        for (int j = 0; j < 8; j++) {
            int col = wn * 64 + j * 8 + t4 * 2;
            if (row0 < M) {
                float v0 = scale * (acc[i][j][0] + bias[j].x);
                float v1 = scale * (acc[i][j][1] + bias[j].y);
                if (mode == 1) {
                    v0 = (v0 > 0.f) ? v0 : expm1f(v0);
                    v1 = (v1 > 0.f) ? v1 : expm1f(v1);
                    ps[j * 2] += v0; pq[j * 2] += v0 * v0;
                    ps[j * 2 + 1] += v1; pq[j * 2 + 1] += v1 * v1;
                }
                *(float2*)(C + (size_t)row0 * D + col) = make_float2(v0, v1);
                if (Cshadow) {
                    uint2 s = make_uint2(f2tf32(v0), f2tf32(v1));
                    *(uint2*)(Cshadow + (size_t)row0 * D + col) = s;
                }
            }
            if (row1 < M) {
                float v0 = scale * (acc[i][j][2] + bias[j].x);
                float v1 = scale * (acc[i][j][3] + bias[j].y);
                if (mode == 1) {
                    v0 = (v0 > 0.f) ? v0 : expm1f(v0);
                    v1 = (v1 > 0.f) ? v1 : expm1f(v1);
                    ps[j * 2] += v0; pq[j * 2] += v0 * v0;
                    ps[j * 2 + 1] += v1; pq[j * 2 + 1] += v1 * v1;
                }
                *(float2*)(C + (size_t)row1 * D + col) = make_float2(v0, v1);
                if (Cshadow) {
                    uint2 s = make_uint2(f2tf32(v0), f2tf32(v1));
                    *(uint2*)(Cshadow + (size_t)row1 * D + col) = s;
                }
            }
        }
    }

    if (mode == 1) {
#pragma unroll
        for (int j = 0; j < 8; j++) {
            int col = wn * 64 + j * 8 + t4 * 2;
            atomicAdd(&ssum[col], ps[j * 2]);
            atomicAdd(&ssq[col], pq[j * 2]);
            atomicAdd(&ssum[col + 1], ps[j * 2 + 1]);
            atomicAdd(&ssq[col + 1], pq[j * 2 + 1]);
        }
        __syncthreads();
        if (tid < 128) {
            atomicAdd(&colsum[tid], ssum[tid]);
            atomicAdd(&colsq[tid], ssq[tid]);
        }
    }
}

// ---------------- batchnorm ----------------
__global__ void k_bn_prep(const float* __restrict__ stats, const float* __restrict__ g,
                          const float* __restrict__ b, float invN, float* __restrict__ ac) {
    int t = threadIdx.x;  // 128
    float m = stats[t] * invN;
    float var = stats[128 + t] * invN - m * m;
    float r = rsqrtf(var + 1e-5f);
    float a = g[t] * r;
    ac[t] = a;
    ac[128 + t] = b[t] - m * a;
}
// applies BN in place; optionally writes TF32 shadow
__global__ void k_bn_apply(float4* __restrict__ x, int n4, const float* __restrict__ ac,
                           uint4* __restrict__ shadow) {
    __shared__ float sa[128], sc[128];
    if (threadIdx.x < 128) { sa[threadIdx.x] = ac[threadIdx.x]; sc[threadIdx.x] = ac[128 + threadIdx.x]; }
    __syncthreads();
    int stride = gridDim.x * blockDim.x;
    for (int i = blockIdx.x * blockDim.x + threadIdx.x; i < n4; i += stride) {
        float4 v = x[i];
        int c = (i & 31) * 4;
        v.x = v.x * sa[c + 0] + sc[c + 0];
        v.y = v.y * sa[c + 1] + sc[c + 1];
        v.z = v.z * sa[c + 2] + sc[c + 2];
        v.w = v.w * sa[c + 3] + sc[c + 3];
        x[i] = v;
        if (shadow) {
            uint4 u;
            u.x = f2tf32(v.x); u.y = f2tf32(v.y); u.z = f2tf32(v.z); u.w = f2tf32(v.w);
            shadow[i] = u;
        }
    }
}

// ---------------- host side ----------------
static void* sym_addr(const void* sym) {
    void* p = nullptr;
    cudaGetSymbolAddress(&p, sym);
    return p;
}

static void build_csr(const int* src, const int* dst, int E, int n,
                      int* off, int* edges, int* cursor, int* bsum) {
    k_zero_i<<<(n + 255) / 256, 256>>>(cursor, n);
    k_count<<<(E + 255) / 256, 256>>>(dst, E, cursor);
    int nb = (n + 1023) / 1024;
    k_scan_block<<<nb, 1024>>>(cursor, n, off, bsum);
    k_scan_bsum<<<1, 1024>>>(bsum, nb);
    k_scan_add<<<nb, 1024>>>(off, n, bsum);
    k_copy_i<<<(n + 255) / 256, 256>>>(cursor, off, n);
    k_fill<<<(E + 255) / 256, 256>>>(src, dst, E, cursor, edges);
}

extern "C" void kernel_launch(void* const* d_in, const int* in_sizes, int n_in,
                              void* d_out, int out_size) {
    const float* x_student = (const float*)d_in[0];
    const float* x_item    = (const float*)d_in[1];
    const float* Wl_ri = (const float*)d_in[2];
    const float* bl_ri = (const float*)d_in[3];
    const float* Wr_ri = (const float*)d_in[4];
    const float* Wl_rs = (const float*)d_in[5];
    const float* bl_rs = (const float*)d_in[6];
    const float* Wr_rs = (const float*)d_in[7];
    const float* W_p   = (const float*)d_in[8];
    const float* b_p   = (const float*)d_in[9];
    const float* bn_g  = (const float*)d_in[10];
    const float* bn_b  = (const float*)d_in[11];
    const int* resp_src = (const int*)d_in[12];
    const int* resp_dst = (const int*)d_in[13];
    const int* rev_src  = (const int*)d_in[14];
    const int* rev_dst  = (const int*)d_in[15];
    const int* prec_src = (const int*)d_in[16];
    const int* prec_dst = (const int*)d_in[17];

    const int NS = in_sizes[0] / D;
    const int NI = in_sizes[1] / D;
    const int E_resp = in_sizes[12];
    const int E_rev  = in_sizes[14];
    const int E_prec = in_sizes[16];

    uint32_t* aggI = (uint32_t*)sym_addr(g_aggI);
    uint32_t* aggS = (uint32_t*)sym_addr(g_aggS);
    uint32_t* aggP = (uint32_t*)sym_addr(g_aggP);
    uint32_t* xs32 = (uint32_t*)sym_addr(g_xs32);
    uint32_t* xi32 = (uint32_t*)sym_addr(g_xi32);
    uint32_t* w_lri = (uint32_t*)sym_addr(g_w_lri);
    uint32_t* w_rri = (uint32_t*)sym_addr(g_w_rri);
    uint32_t* w_lrs = (uint32_t*)sym_addr(g_w_lrs);
    uint32_t* w_rrs = (uint32_t*)sym_addr(g_w_rrs);
    uint32_t* w_p   = (uint32_t*)sym_addr(g_w_p);
    int* off_resp  = (int*)sym_addr(g_off_resp);
    int* edge_resp = (int*)sym_addr(g_edge_resp);
    int* off_rev   = (int*)sym_addr(g_off_rev);
    int* edge_rev  = (int*)sym_addr(g_edge_rev);
    int* off_prec  = (int*)sym_addr(g_off_prec);
    int* edge_prec = (int*)sym_addr(g_edge_prec);
    int* cursor = (int*)sym_addr(g_cursor);
    int* bsum   = (int*)sym_addr(g_bsum);
    float* colstats = (float*)sym_addr(g_colstats);
    float* bn_ac    = (float*)sym_addr(g_bn_ac);

    float* xi_out = (float*)d_out;                 // NI x D
    float* xs_out = xi_out + (size_t)NI * D;       // NS x D

    // opt-in dynamic smem for the GEMM (idempotent)
    static int smem_set = 0;
    const int SMEM_DYN = 8 * TILE * 4;  // 81920 B
    if (!smem_set) {
        cudaFuncSetAttribute(k_gemm_tc, cudaFuncAttributeMaxDynamicSharedMemorySize, SMEM_DYN);
        smem_set = 1;
    }

    // CSR graphs (depend only on inputs; rebuilt every call)
    build_csr(resp_src, resp_dst, E_resp, NI, off_resp, edge_resp, cursor, bsum);
    build_csr(rev_src, rev_dst, E_rev, NS, off_rev, edge_rev, cursor, bsum);
    build_csr(prec_src, prec_dst, E_prec, NS, off_prec, edge_prec, cursor, bsum);

    // TF32 shadows of inputs and weights
    {
        int n4s = NS * D / 4, n4i = NI * D / 4;
        k_cvt<<<(n4s + 255) / 256, 256>>>((const float4*)x_student, (uint4*)xs32, n4s);
        k_cvt<<<(n4i + 255) / 256, 256>>>((const float4*)x_item, (uint4*)xi32, n4i);
        int n4w = 2 * D * D / 4;
        k_cvt<<<(n4w + 255) / 256, 256>>>((const float4*)Wl_ri, (uint4*)w_lri, n4w);
        k_cvt<<<(n4w + 255) / 256, 256>>>((const float4*)Wr_ri, (uint4*)w_rri, n4w);
        k_cvt<<<(n4w + 255) / 256, 256>>>((const float4*)Wl_rs, (uint4*)w_lrs, n4w);
        k_cvt<<<(n4w + 255) / 256, 256>>>((const float4*)Wr_rs, (uint4*)w_rrs, n4w);
        k_cvt<<<(n4w + 255) / 256, 256>>>((const float4*)W_p,   (uint4*)w_p,   n4w);
    }

    const float* xs_cur = x_student;
    const float* xi_cur = x_item;

    const int gtI = (NI + 7) / 8;   // gather: 8 warps / block
    const int gtS = (NS + 7) / 8;
    const int gbI = (NI + 127) / 128;
    const int gbS = (NS + 127) / 128;

    for (int l = 0; l < 2; l++) {
        const size_t wOff = (size_t)l * D * D;
        const size_t bOff = (size_t)l * D;
        const int last = (l == 1);

        // aggregations (read old fp32 xs/xi, emit tf32)
        k_gather<<<gtI, 256>>>((const float4*)xs_cur, edge_resp, off_resp,
                               (uint4*)aggI, NI, 1);
        k_gather<<<gtS, 256>>>((const float4*)xi_cur, edge_rev, off_rev,
                               (uint4*)aggS, NS, 1);
        k_gather<<<gtS, 256>>>((const float4*)xs_cur, edge_prec, off_prec,
                               (uint4*)aggP, NS, 0);

        // item path: fused TF32 GEMM (K=256) + bias + ELU + BN stats
        k_zero_f<<<1, 256>>>(colstats, 256);
        k_gemm_tc<<<gbI, 256, SMEM_DYN>>>(aggI, xi32, nullptr,
                                          w_lri + wOff, w_rri + wOff, nullptr,
                                          bl_ri + bOff, nullptr,
                                          1.0f, 1, 2, NI, xi_out, nullptr,
                                          colstats, colstats + 128);
        k_bn_prep<<<1, 128>>>(colstats, bn_g + bOff, bn_b + bOff,
                              1.0f / (float)NI, bn_ac);
        k_bn_apply<<<512, 256>>>((float4*)xi_out, NI * 32, bn_ac,
                                 last ? nullptr : (uint4*)xi32);

        // student path: fused TF32 GEMM (K=384), out = 0.5*(sum + bl_rs + b_p)
        k_gemm_tc<<<gbS, 256, SMEM_DYN>>>(aggS, xs32, aggP,
                                          w_lrs + wOff, w_rrs + wOff, w_p + wOff,
                                          bl_rs + bOff, b_p + bOff,
                                          0.5f, 0, 3, NS, xs_out,
                                          last ? nullptr : xs32,
                                          nullptr, nullptr);

        xs_cur = xs_out;
        xi_cur = xi_out;
    }
}

// round 8
// speedup vs baseline: 1.9710x; 1.1798x over previous
#include <cuda_runtime.h>
#include <cuda_fp16.h>
#include <math.h>
#include <stdint.h>

#define D 128
#define NS_MAX 100000
#define NI_MAX 20000
#define E_MAX  600000

// ---------------- device scratch (static, no allocation) ----------------
// fp16 GEMM operands
__device__ unsigned short g_aggI[(size_t)NI_MAX * D];
__device__ unsigned short g_aggS[(size_t)NS_MAX * D];
__device__ unsigned short g_aggP[(size_t)NS_MAX * D];
__device__ unsigned short g_xs16[(size_t)NS_MAX * D];
__device__ unsigned short g_xi16[(size_t)NI_MAX * D];
__device__ unsigned short g_w_lri[2 * D * D];
__device__ unsigned short g_w_rri[2 * D * D];
__device__ unsigned short g_w_lrs[2 * D * D];
__device__ unsigned short g_w_rrs[2 * D * D];
__device__ unsigned short g_w_p[2 * D * D];

__device__ int g_off_resp[NI_MAX + 1];
__device__ int g_edge_resp[E_MAX];
__device__ int g_off_rev[NS_MAX + 1];
__device__ int g_edge_rev[E_MAX];
__device__ int g_off_prec[NS_MAX + 1];
__device__ int g_edge_prec[E_MAX];

__device__ int   g_cursor[NS_MAX + 1];
__device__ int   g_bsum[1024];
__device__ float g_colstats[256];   // [0:128) sum, [128:256) sumsq
__device__ float g_bn_ac[256];      // [0:128) a,   [128:256) c

__device__ __forceinline__ uint32_t pack_h2(float a, float b) {
    __half2 h = __float22half2_rn(make_float2(a, b));
    return *(uint32_t*)&h;
}

// ---------------- small utility kernels ----------------
__global__ void k_zero_i(int* __restrict__ p, int n) {
    int i = blockIdx.x * blockDim.x + threadIdx.x;
    if (i < n) p[i] = 0;
}
__global__ void k_zero_f(float* __restrict__ p, int n) {
    int i = blockIdx.x * blockDim.x + threadIdx.x;
    if (i < n) p[i] = 0.f;
}
// float4 -> 4 halves (uint2)
__global__ void k_cvt(const float4* __restrict__ in, uint2* __restrict__ out, int n4) {
    int i = blockIdx.x * blockDim.x + threadIdx.x;
    if (i < n4) {
        float4 v = in[i];
        uint2 u;
        u.x = pack_h2(v.x, v.y);
        u.y = pack_h2(v.z, v.w);
        out[i] = u;
    }
}
__global__ void k_count(const int* __restrict__ dst, int E, int* __restrict__ cnt) {
    int i = blockIdx.x * blockDim.x + threadIdx.x;
    if (i < E) atomicAdd(&cnt[dst[i]], 1);
}
__global__ void k_scan_block(const int* __restrict__ cnt, int n,
                             int* __restrict__ off, int* __restrict__ bsum) {
    __shared__ int sh[1024];
    int tid = threadIdx.x;
    int i = blockIdx.x * 1024 + tid;
    int v = (i < n) ? cnt[i] : 0;
    sh[tid] = v;
    __syncthreads();
    for (int d = 1; d < 1024; d <<= 1) {
        int t = 0;
        if (tid >= d) t = sh[tid - d];
        __syncthreads();
        if (tid >= d) sh[tid] += t;
        __syncthreads();
    }
    if (i < n) off[i + 1] = sh[tid];
    if (tid == 1023) bsum[blockIdx.x] = sh[1023];
}
__global__ void k_scan_bsum(int* __restrict__ bsum, int nb) {
    __shared__ int sh[1024];
    int tid = threadIdx.x;
    int v = (tid < nb) ? bsum[tid] : 0;
    sh[tid] = v;
    __syncthreads();
    for (int d = 1; d < 1024; d <<= 1) {
        int t = 0;
        if (tid >= d) t = sh[tid - d];
        __syncthreads();
        if (tid >= d) sh[tid] += t;
        __syncthreads();
    }
    if (tid < nb) bsum[tid] = sh[tid] - v;   // exclusive
}
__global__ void k_scan_add(int* __restrict__ off, int n, const int* __restrict__ bsum) {
    int i = blockIdx.x * 1024 + threadIdx.x;
    if (i < n) off[i + 1] += bsum[blockIdx.x];
    if (i == 0) off[0] = 0;
}
__global__ void k_copy_i(int* __restrict__ dst, const int* __restrict__ src, int n) {
    int i = blockIdx.x * blockDim.x + threadIdx.x;
    if (i < n) dst[i] = src[i];
}
__global__ void k_fill(const int* __restrict__ src, const int* __restrict__ dst, int E,
                       int* __restrict__ cursor, int* __restrict__ edges) {
    int e = blockIdx.x * blockDim.x + threadIdx.x;
    if (e < E) {
        int d = dst[e];
        int p = atomicAdd(&cursor[d], 1);
        edges[p] = src[e];
    }
}

// ---------------- CSR gather aggregation ----------------
// fp32 accumulate, fp16 output (GEMM A-operand)
__global__ void k_gather(const float4* __restrict__ x, const int* __restrict__ edges,
                         const int* __restrict__ off, uint2* __restrict__ out,
                         int n_dst, int domean) {
    int w = (blockIdx.x * blockDim.x + threadIdx.x) >> 5;
    int lane = threadIdx.x & 31;
    if (w >= n_dst) return;
    int beg = off[w], end = off[w + 1];
    float4 acc = make_float4(0.f, 0.f, 0.f, 0.f);
    for (int e = beg; e < end; e++) {
        int s = edges[e];
        float4 v = __ldg(&x[(size_t)s * 32 + lane]);
        acc.x += v.x; acc.y += v.y; acc.z += v.z; acc.w += v.w;
    }
    if (domean) {
        int c = end - beg; if (c < 1) c = 1;
        float inv = 1.0f / (float)c;
        acc.x *= inv; acc.y *= inv; acc.z *= inv; acc.w *= inv;
    }
    uint2 o;
    o.x = pack_h2(acc.x, acc.y);
    o.y = pack_h2(acc.z, acc.w);
    out[(size_t)w * 32 + lane] = o;
}

// ---------------- FP16 tensor-core GEMM, cp.async 4-stage pipeline --------------
// C = scale * (sum_a A_a @ W_a^T + b0 + b1); fp16 operands, fp32 accumulation.
// mode==1: ELU + per-column sum/sumsq (BN stats). Cshadow: optional fp16 copy of C.
// BM=128, BN=128(=D), BK=32 halves; 8 warps (4x2), warp tile 32x64.
// SMEM row: 32 halves = 16 words, padded to LDW=20 words (conflict-free).

#define BK   32
#define LDW  20
#define TILEW (128 * LDW)            // words per matrix per stage

__device__ __forceinline__ void cp16(uint32_t dst, const void* src, int srcsize) {
    asm volatile("cp.async.cg.shared.global [%0], [%1], 16, %2;"
                 :: "r"(dst), "l"(src), "r"(srcsize));
}

__device__ __forceinline__ void mma_f16(float c[4],
                                        uint32_t a0, uint32_t a1, uint32_t a2, uint32_t a3,
                                        uint32_t b0, uint32_t b1) {
    asm volatile(
        "mma.sync.aligned.m16n8k16.row.col.f32.f16.f16.f32 "
        "{%0,%1,%2,%3}, {%4,%5,%6,%7}, {%8,%9}, {%0,%1,%2,%3};"
        : "+f"(c[0]), "+f"(c[1]), "+f"(c[2]), "+f"(c[3])
        : "r"(a0), "r"(a1), "r"(a2), "r"(a3), "r"(b0), "r"(b1));
}

__global__ __launch_bounds__(256, 2) void k_gemm_tc(
    const unsigned short* __restrict__ A0, const unsigned short* __restrict__ A1,
    const unsigned short* __restrict__ A2,
    const unsigned short* __restrict__ W0, const unsigned short* __restrict__ W1,
    const unsigned short* __restrict__ W2,
    const float* __restrict__ b0, const float* __restrict__ b1,
    float scale, int mode, int NA, int M,
    float* __restrict__ C, unsigned short* __restrict__ Cshadow,
    float* __restrict__ colsum, float* __restrict__ colsq) {

    extern __shared__ uint32_t smemu[];
    uint32_t* sA = smemu;             // 4 stages * TILEW
    uint32_t* sB = smemu + 4 * TILEW; // 4 stages * TILEW
    __shared__ float ssum[128], ssq[128];

    const int tid  = threadIdx.x;
    const int m0   = blockIdx.x * 128;
    const int warp = tid >> 5;
    const int lane = tid & 31;
    const int wm   = warp >> 1;      // 0..3
    const int wn   = warp & 1;       // 0..1
    const int g    = lane >> 2;      // 0..7
    const int t4   = lane & 3;       // 0..3

    // stage load mapping: per matrix 128 rows x 64B = 512 x 16B chunks, 2/thread
    const int c0 = tid * 2;

    const unsigned short* Aarr[3] = {A0, A1, A2};
    const unsigned short* Warr[3] = {W0, W1, W2};

    const uint32_t sA_addr = (uint32_t)__cvta_generic_to_shared(sA);
    const uint32_t sB_addr = (uint32_t)__cvta_generic_to_shared(sB);

    float acc[2][8][4];
#pragma unroll
    for (int i = 0; i < 2; i++)
#pragma unroll
        for (int j = 0; j < 8; j++)
#pragma unroll
            for (int c = 0; c < 4; c++) acc[i][j][c] = 0.f;

    const int KT = NA * (D / BK);    // 4 per matrix

    auto issue = [&](int t, int st) {
        int a  = t >> 2;
        int k0 = (t & 3) * BK;       // halves
        const unsigned short* A = Aarr[a];
        const unsigned short* W = Warr[a];
        uint32_t dA = sA_addr + st * (TILEW * 4);
        uint32_t dB = sB_addr + st * (TILEW * 4);
#pragma unroll
        for (int i = 0; i < 2; i++) {
            int c   = c0 + i;
            int row = c >> 2;        // 0..127
            int seg = c & 3;         // 0..3 (16B chunks of the 64B row)
            uint32_t doff = (uint32_t)(row * LDW + seg * 4) * 4;
            int szA = (m0 + row < M) ? 16 : 0;
            cp16(dA + doff, A + (size_t)(m0 + row) * D + k0 + seg * 8, szA);
            cp16(dB + doff, W + (size_t)row * D + k0 + seg * 8, 16);
        }
        asm volatile("cp.async.commit_group;");
    };

    // prologue: 3 stages in flight
#pragma unroll
    for (int s = 0; s < 3; s++) issue(s, s);

    for (int t = 0; t < KT; t++) {
        asm volatile("cp.async.wait_group 2;");
        __syncthreads();

        if (t + 3 < KT) issue(t + 3, (t + 3) & 3);
        else asm volatile("cp.async.commit_group;");

        const uint32_t* cA = sA + (t & 3) * TILEW;
        const uint32_t* cB = sB + (t & 3) * TILEW;
#pragma unroll
        for (int kk2 = 0; kk2 < 2; kk2++) {      // two k16 steps per BK=32
            const int wk = kk2 * 8;              // word offset
            uint32_t af[2][4];
#pragma unroll
            for (int i = 0; i < 2; i++) {
                int mb = wm * 32 + i * 16;
                af[i][0] = cA[(mb + g)     * LDW + wk + t4];
                af[i][1] = cA[(mb + g + 8) * LDW + wk + t4];
                af[i][2] = cA[(mb + g)     * LDW + wk + t4 + 4];
                af[i][3] = cA[(mb + g + 8) * LDW + wk + t4 + 4];
            }
#pragma unroll
            for (int j = 0; j < 8; j++) {
                int nb = wn * 64 + j * 8;
                uint32_t bf0 = cB[(nb + g) * LDW + wk + t4];
                uint32_t bf1 = cB[(nb + g) * LDW + wk + t4 + 4];
                mma_f16(acc[0][j], af[0][0], af[0][1], af[0][2], af[0][3], bf0, bf1);
                mma_f16(acc[1][j], af[1][0], af[1][1], af[1][2], af[1][3], bf0, bf1);
            }
        }
        __syncthreads();
    }

    // ---------------- epilogue ----------------
    if (mode == 1) {
        if (tid < 128) { ssum[tid] = 0.f; ssq[tid] = 0.f; }
        __syncthreads();
    }

    float2 bias[8];
#pragma unroll
    for (int j = 0; j < 8; j++) {
        int col = wn * 64 + j * 8 + t4 * 2;
        bias[j].x = b0[col]     + (b1 ? b1[col]     : 0.f);
        bias[j].y = b0[col + 1] + (b1 ? b1[col + 1] : 0.f);
    }

    float ps[16], pq[16];
#pragma unroll
    for (int j = 0; j < 16; j++) { ps[j] = 0.f; pq[j] = 0.f; }

#pragma unroll
    for (int i = 0; i < 2; i++) {
        int row0 = m0 + wm * 32 + i * 16 + g;
        int row1 = row0 + 8;
#pragma unroll
        for (int j = 0; j < 8; j++) {
            int col = wn * 64 + j * 8 + t4 * 2;
            if (row0 < M) {
                float v0 = scale * (acc[i][j][0] + bias[j].x);
                float v1 = scale * (acc[i][j][1] + bias[j].y);
                if (mode == 1) {
                    v0 = (v0 > 0.f) ? v0 : expm1f(v0);
                    v1 = (v1 > 0.f) ? v1 : expm1f(v1);
                    ps[j * 2] += v0; pq[j * 2] += v0 * v0;
                    ps[j * 2 + 1] += v1; pq[j * 2 + 1] += v1 * v1;
                }
                *(float2*)(C + (size_t)row0 * D + col) = make_float2(v0, v1);
                if (Cshadow)
                    *(uint32_t*)(Cshadow + (size_t)row0 * D + col) = pack_h2(v0, v1);
            }
            if (row1 < M) {
                float v0 = scale * (acc[i][j][2] + bias[j].x);
                float v1 = scale * (acc[i][j][3] + bias[j].y);
                if (mode == 1) {
                    v0 = (v0 > 0.f) ? v0 : expm1f(v0);
                    v1 = (v1 > 0.f) ? v1 : expm1f(v1);
                    ps[j * 2] += v0; pq[j * 2] += v0 * v0;
                    ps[j * 2 + 1] += v1; pq[j * 2 + 1] += v1 * v1;
                }
                *(float2*)(C + (size_t)row1 * D + col) = make_float2(v0, v1);
                if (Cshadow)
                    *(uint32_t*)(Cshadow + (size_t)row1 * D + col) = pack_h2(v0, v1);
            }
        }
    }

    if (mode == 1) {
#pragma unroll
        for (int j = 0; j < 8; j++) {
            int col = wn * 64 + j * 8 + t4 * 2;
            atomicAdd(&ssum[col], ps[j * 2]);
            atomicAdd(&ssq[col], pq[j * 2]);
            atomicAdd(&ssum[col + 1], ps[j * 2 + 1]);
            atomicAdd(&ssq[col + 1], pq[j * 2 + 1]);
        }
        __syncthreads();
        if (tid < 128) {
            atomicAdd(&colsum[tid], ssum[tid]);
            atomicAdd(&colsq[tid], ssq[tid]);
        }
    }
}

// ---------------- batchnorm ----------------
__global__ void k_bn_prep(const float* __restrict__ stats, const float* __restrict__ g,
                          const float* __restrict__ b, float invN, float* __restrict__ ac) {
    int t = threadIdx.x;  // 128
    float m = stats[t] * invN;
    float var = stats[128 + t] * invN - m * m;
    float r = rsqrtf(var + 1e-5f);
    float a = g[t] * r;
    ac[t] = a;
    ac[128 + t] = b[t] - m * a;
}
// applies BN in place; optionally writes fp16 shadow
__global__ void k_bn_apply(float4* __restrict__ x, int n4, const float* __restrict__ ac,
                           uint2* __restrict__ shadow) {
    __shared__ float sa[128], sc[128];
    if (threadIdx.x < 128) { sa[threadIdx.x] = ac[threadIdx.x]; sc[threadIdx.x] = ac[128 + threadIdx.x]; }
    __syncthreads();
    int stride = gridDim.x * blockDim.x;
    for (int i = blockIdx.x * blockDim.x + threadIdx.x; i < n4; i += stride) {
        float4 v = x[i];
        int c = (i & 31) * 4;
        v.x = v.x * sa[c + 0] + sc[c + 0];
        v.y = v.y * sa[c + 1] + sc[c + 1];
        v.z = v.z * sa[c + 2] + sc[c + 2];
        v.w = v.w * sa[c + 3] + sc[c + 3];
        x[i] = v;
        if (shadow) {
            uint2 u;
            u.x = pack_h2(v.x, v.y);
            u.y = pack_h2(v.z, v.w);
            shadow[i] = u;
        }
    }
}

// ---------------- host side ----------------
static void* sym_addr(const void* sym) {
    void* p = nullptr;
    cudaGetSymbolAddress(&p, sym);
    return p;
}

static void build_csr(const int* src, const int* dst, int E, int n,
                      int* off, int* edges, int* cursor, int* bsum) {
    k_zero_i<<<(n + 255) / 256, 256>>>(cursor, n);
    k_count<<<(E + 255) / 256, 256>>>(dst, E, cursor);
    int nb = (n + 1023) / 1024;
    k_scan_block<<<nb, 1024>>>(cursor, n, off, bsum);
    k_scan_bsum<<<1, 1024>>>(bsum, nb);
    k_scan_add<<<nb, 1024>>>(off, n, bsum);
    k_copy_i<<<(n + 255) / 256, 256>>>(cursor, off, n);
    k_fill<<<(E + 255) / 256, 256>>>(src, dst, E, cursor, edges);
}

extern "C" void kernel_launch(void* const* d_in, const int* in_sizes, int n_in,
                              void* d_out, int out_size) {
    const float* x_student = (const float*)d_in[0];
    const float* x_item    = (const float*)d_in[1];
    const float* Wl_ri = (const float*)d_in[2];
    const float* bl_ri = (const float*)d_in[3];
    const float* Wr_ri = (const float*)d_in[4];
    const float* Wl_rs = (const float*)d_in[5];
    const float* bl_rs = (const float*)d_in[6];
    const float* Wr_rs = (const float*)d_in[7];
    const float* W_p   = (const float*)d_in[8];
    const float* b_p   = (const float*)d_in[9];
    const float* bn_g  = (const float*)d_in[10];
    const float* bn_b  = (const float*)d_in[11];
    const int* resp_src = (const int*)d_in[12];
    const int* resp_dst = (const int*)d_in[13];
    const int* rev_src  = (const int*)d_in[14];
    const int* rev_dst  = (const int*)d_in[15];
    const int* prec_src = (const int*)d_in[16];
    const int* prec_dst = (const int*)d_in[17];

    const int NS = in_sizes[0] / D;
    const int NI = in_sizes[1] / D;
    const int E_resp = in_sizes[12];
    const int E_rev  = in_sizes[14];
    const int E_prec = in_sizes[16];

    unsigned short* aggI = (unsigned short*)sym_addr(g_aggI);
    unsigned short* aggS = (unsigned short*)sym_addr(g_aggS);
    unsigned short* aggP = (unsigned short*)sym_addr(g_aggP);
    unsigned short* xs16 = (unsigned short*)sym_addr(g_xs16);
    unsigned short* xi16 = (unsigned short*)sym_addr(g_xi16);
    unsigned short* w_lri = (unsigned short*)sym_addr(g_w_lri);
    unsigned short* w_rri = (unsigned short*)sym_addr(g_w_rri);
    unsigned short* w_lrs = (unsigned short*)sym_addr(g_w_lrs);
    unsigned short* w_rrs = (unsigned short*)sym_addr(g_w_rrs);
    unsigned short* w_p   = (unsigned short*)sym_addr(g_w_p);
    int* off_resp  = (int*)sym_addr(g_off_resp);
    int* edge_resp = (int*)sym_addr(g_edge_resp);
    int* off_rev   = (int*)sym_addr(g_off_rev);
    int* edge_rev  = (int*)sym_addr(g_edge_rev);
    int* off_prec  = (int*)sym_addr(g_off_prec);
    int* edge_prec = (int*)sym_addr(g_edge_prec);
    int* cursor = (int*)sym_addr(g_cursor);
    int* bsum   = (int*)sym_addr(g_bsum);
    float* colstats = (float*)sym_addr(g_colstats);
    float* bn_ac    = (float*)sym_addr(g_bn_ac);

    float* xi_out = (float*)d_out;                 // NI x D
    float* xs_out = xi_out + (size_t)NI * D;       // NS x D

    static int smem_set = 0;
    const int SMEM_DYN = 8 * TILEW * 4;  // 81920 B
    if (!smem_set) {
        cudaFuncSetAttribute(k_gemm_tc, cudaFuncAttributeMaxDynamicSharedMemorySize, SMEM_DYN);
        smem_set = 1;
    }

    // CSR graphs (depend only on inputs; rebuilt every call)
    build_csr(resp_src, resp_dst, E_resp, NI, off_resp, edge_resp, cursor, bsum);
    build_csr(rev_src, rev_dst, E_rev, NS, off_rev, edge_rev, cursor, bsum);
    build_csr(prec_src, prec_dst, E_prec, NS, off_prec, edge_prec, cursor, bsum);

    // fp16 shadows of inputs and weights
    {
        int n4s = NS * D / 4, n4i = NI * D / 4;
        k_cvt<<<(n4s + 255) / 256, 256>>>((const float4*)x_student, (uint2*)xs16, n4s);
        k_cvt<<<(n4i + 255) / 256, 256>>>((const float4*)x_item, (uint2*)xi16, n4i);
        int n4w = 2 * D * D / 4;
        k_cvt<<<(n4w + 255) / 256, 256>>>((const float4*)Wl_ri, (uint2*)w_lri, n4w);
        k_cvt<<<(n4w + 255) / 256, 256>>>((const float4*)Wr_ri, (uint2*)w_rri, n4w);
        k_cvt<<<(n4w + 255) / 256, 256>>>((const float4*)Wl_rs, (uint2*)w_lrs, n4w);
        k_cvt<<<(n4w + 255) / 256, 256>>>((const float4*)Wr_rs, (uint2*)w_rrs, n4w);
        k_cvt<<<(n4w + 255) / 256, 256>>>((const float4*)W_p,   (uint2*)w_p,   n4w);
    }

    const float* xs_cur = x_student;
    const float* xi_cur = x_item;

    const int gtI = (NI + 7) / 8;   // gather: 8 warps / block
    const int gtS = (NS + 7) / 8;
    const int gbI = (NI + 127) / 128;
    const int gbS = (NS + 127) / 128;

    for (int l = 0; l < 2; l++) {
        const size_t wOff = (size_t)l * D * D;
        const size_t bOff = (size_t)l * D;
        const int last = (l == 1);

        // aggregations (read old fp32 xs/xi, emit fp16)
        k_gather<<<gtI, 256>>>((const float4*)xs_cur, edge_resp, off_resp,
                               (uint2*)aggI, NI, 1);
        k_gather<<<gtS, 256>>>((const float4*)xi_cur, edge_rev, off_rev,
                               (uint2*)aggS, NS, 1);
        k_gather<<<gtS, 256>>>((const float4*)xs_cur, edge_prec, off_prec,
                               (uint2*)aggP, NS, 0);

        // item path: fp16 GEMM (K=256) + bias + ELU + BN stats
        k_zero_f<<<1, 256>>>(colstats, 256);
        k_gemm_tc<<<gbI, 256, SMEM_DYN>>>(aggI, xi16, nullptr,
                                          w_lri + wOff, w_rri + wOff, nullptr,
                                          bl_ri + bOff, nullptr,
                                          1.0f, 1, 2, NI, xi_out, nullptr,
                                          colstats, colstats + 128);
        k_bn_prep<<<1, 128>>>(colstats, bn_g + bOff, bn_b + bOff,
                              1.0f / (float)NI, bn_ac);
        k_bn_apply<<<512, 256>>>((float4*)xi_out, NI * 32, bn_ac,
                                 last ? nullptr : (uint2*)xi16);

        // student path: fp16 GEMM (K=384), out = 0.5*(sum + bl_rs + b_p)
        k_gemm_tc<<<gbS, 256, SMEM_DYN>>>(aggS, xs16, aggP,
                                          w_lrs + wOff, w_rrs + wOff, w_p + wOff,
                                          bl_rs + bOff, b_p + bOff,
                                          0.5f, 0, 3, NS, xs_out,
                                          last ? nullptr : xs16,
                                          nullptr, nullptr);

        xs_cur = xs_out;
        xi_cur = xi_out;
    }
}

// round 9
// speedup vs baseline: 2.2028x; 1.1176x over previous
#include <cuda_runtime.h>
#include <cuda_fp16.h>
#include <math.h>
#include <stdint.h>

#define D 128
#define NS_MAX 100000
#define NI_MAX 20000
#define E_MAX  600000

// ---------------- device scratch (static, no allocation) ----------------
// fp16 GEMM operands
__device__ unsigned short g_aggI[(size_t)NI_MAX * D];
__device__ unsigned short g_aggS[(size_t)NS_MAX * D];
__device__ unsigned short g_aggP[(size_t)NS_MAX * D];
__device__ unsigned short g_xs16[(size_t)NS_MAX * D];
__device__ unsigned short g_xi16[(size_t)NI_MAX * D];
__device__ unsigned short g_w_lri[2 * D * D];
__device__ unsigned short g_w_rri[2 * D * D];
__device__ unsigned short g_w_lrs[2 * D * D];
__device__ unsigned short g_w_rrs[2 * D * D];
__device__ unsigned short g_w_p[2 * D * D];

__device__ int g_off_resp[NI_MAX + 1];
__device__ int g_edge_resp[E_MAX];
__device__ int g_off_rev[NS_MAX + 1];
__device__ int g_edge_rev[E_MAX];
__device__ int g_off_prec[NS_MAX + 1];
__device__ int g_edge_prec[E_MAX];

__device__ int g_cnt_resp[NI_MAX];
__device__ int g_cnt_rev[NS_MAX];
__device__ int g_cnt_prec[NS_MAX];

__device__ int   g_bsum[1024];
__device__ float g_colstats[256];   // [0:128) sum, [128:256) sumsq
__device__ float g_bn_ac[256];      // [0:128) a,   [128:256) c

__device__ __forceinline__ uint32_t pack_h2(float a, float b) {
    __half2 h = __float22half2_rn(make_float2(a, b));
    return *(uint32_t*)&h;
}

// ---------------- fused conversion: all fp32 inputs -> fp16 shadows -------------
__global__ void k_cvt_all(
    const float4* __restrict__ xs, const float4* __restrict__ xi,
    const float4* __restrict__ w0, const float4* __restrict__ w1,
    const float4* __restrict__ w2, const float4* __restrict__ w3,
    const float4* __restrict__ w4,
    uint2* __restrict__ oxs, uint2* __restrict__ oxi,
    uint2* __restrict__ ow0, uint2* __restrict__ ow1,
    uint2* __restrict__ ow2, uint2* __restrict__ ow3,
    uint2* __restrict__ ow4,
    int n4s, int n4i, int n4w) {
    int i = blockIdx.x * blockDim.x + threadIdx.x;
    const float4* in; uint2* out; int j;
    if (i < n4s) { in = xs; out = oxs; j = i; }
    else {
        i -= n4s;
        if (i < n4i) { in = xi; out = oxi; j = i; }
        else {
            i -= n4i;
            int ws = i / n4w; j = i - ws * n4w;
            if (ws >= 5) return;
            switch (ws) {
                case 0: in = w0; out = ow0; break;
                case 1: in = w1; out = ow1; break;
                case 2: in = w2; out = ow2; break;
                case 3: in = w3; out = ow3; break;
                default: in = w4; out = ow4; break;
            }
        }
    }
    float4 v = in[j];
    uint2 u; u.x = pack_h2(v.x, v.y); u.y = pack_h2(v.z, v.w);
    out[j] = u;
}

// ---------------- fused CSR build (3 graphs) ----------------
__global__ void k_zero3(int* __restrict__ c1, int n1, int* __restrict__ c2, int n2,
                        int* __restrict__ c3, int n3) {
    int i = blockIdx.x * blockDim.x + threadIdx.x;
    if (i < n1) c1[i] = 0;
    else { i -= n1; if (i < n2) c2[i] = 0;
           else { i -= n2; if (i < n3) c3[i] = 0; } }
}
__global__ void k_count3(const int* __restrict__ d1, int E1, int* __restrict__ c1,
                         const int* __restrict__ d2, int E2, int* __restrict__ c2,
                         const int* __restrict__ d3, int E3, int* __restrict__ c3) {
    int i = blockIdx.x * blockDim.x + threadIdx.x;
    if (i < E1) atomicAdd(&c1[d1[i]], 1);
    else { i -= E1; if (i < E2) atomicAdd(&c2[d2[i]], 1);
           else { i -= E2; if (i < E3) atomicAdd(&c3[d3[i]], 1); } }
}
// segmented block scan: seg0 blocks [0,nb1), seg1 [nb1,nb1+nb2), seg2 rest
__global__ void k_scan_block3(
    const int* __restrict__ c1, int n1, int* __restrict__ o1, int nb1,
    const int* __restrict__ c2, int n2, int* __restrict__ o2, int nb2,
    const int* __restrict__ c3, int n3, int* __restrict__ o3,
    int* __restrict__ bsum) {
    __shared__ int sh[1024];
    int tid = threadIdx.x;
    int b = blockIdx.x;
    const int* cnt; int* off; int n; int lb;
    if (b < nb1)            { cnt = c1; off = o1; n = n1; lb = b; }
    else if (b < nb1 + nb2) { cnt = c2; off = o2; n = n2; lb = b - nb1; }
    else                    { cnt = c3; off = o3; n = n3; lb = b - nb1 - nb2; }
    int i = lb * 1024 + tid;
    int v = (i < n) ? cnt[i] : 0;
    sh[tid] = v;
    __syncthreads();
    for (int d = 1; d < 1024; d <<= 1) {
        int t = 0;
        if (tid >= d) t = sh[tid - d];
        __syncthreads();
        if (tid >= d) sh[tid] += t;
        __syncthreads();
    }
    if (i < n) off[i + 1] = sh[tid];
    if (tid == 1023) bsum[blockIdx.x] = sh[1023];
}
// exclusive scan within each of 3 bsum segments (one block)
__global__ void k_scan_bsum3(int* __restrict__ bsum, int nb1, int nb2, int nb3) {
    __shared__ int sh[1024];
    int tid = threadIdx.x;
    int base = 0;
    int nbs[3] = {nb1, nb2, nb3};
    for (int s = 0; s < 3; s++) {
        int nb = nbs[s];
        int v = (tid < nb) ? bsum[base + tid] : 0;
        sh[tid] = v;
        __syncthreads();
        for (int d = 1; d < 1024; d <<= 1) {
            int t = 0;
            if (tid >= d) t = sh[tid - d];
            __syncthreads();
            if (tid >= d) sh[tid] += t;
            __syncthreads();
        }
        if (tid < nb) bsum[base + tid] = sh[tid] - v;
        __syncthreads();
        base += nb;
    }
}
__global__ void k_scan_add3(
    int n1, int* __restrict__ o1, int nb1,
    int n2, int* __restrict__ o2, int nb2,
    int n3, int* __restrict__ o3,
    const int* __restrict__ bsum) {
    int b = blockIdx.x;
    int* off; int n; int lb;
    if (b < nb1)            { off = o1; n = n1; lb = b; }
    else if (b < nb1 + nb2) { off = o2; n = n2; lb = b - nb1; }
    else                    { off = o3; n = n3; lb = b - nb1 - nb2; }
    int i = lb * 1024 + threadIdx.x;
    if (i < n) off[i + 1] += bsum[b];
    if (i == 0) off[0] = 0;
}
// copy off -> cursor (counts reused as cursors)
__global__ void k_copy3(int* __restrict__ c1, const int* __restrict__ o1, int n1,
                        int* __restrict__ c2, const int* __restrict__ o2, int n2,
                        int* __restrict__ c3, const int* __restrict__ o3, int n3) {
    int i = blockIdx.x * blockDim.x + threadIdx.x;
    if (i < n1) c1[i] = o1[i];
    else { i -= n1; if (i < n2) c2[i] = o2[i];
           else { i -= n2; if (i < n3) c3[i] = o3[i]; } }
}
__global__ void k_fill3(
    const int* __restrict__ s1, const int* __restrict__ d1, int E1,
    int* __restrict__ c1, int* __restrict__ e1,
    const int* __restrict__ s2, const int* __restrict__ d2, int E2,
    int* __restrict__ c2, int* __restrict__ e2,
    const int* __restrict__ s3, const int* __restrict__ d3, int E3,
    int* __restrict__ c3, int* __restrict__ e3) {
    int i = blockIdx.x * blockDim.x + threadIdx.x;
    if (i < E1) { int p = atomicAdd(&c1[d1[i]], 1); e1[p] = s1[i]; }
    else { i -= E1;
        if (i < E2) { int p = atomicAdd(&c2[d2[i]], 1); e2[p] = s2[i]; }
        else { i -= E2;
            if (i < E3) { int p = atomicAdd(&c3[d3[i]], 1); e3[p] = s3[i]; } } }
}

// ---------------- fused gather: 3 aggregations in one launch --------------------
// fp16 input rows (uint2 per lane), fp32 accumulate, fp16 output.
// warp w: [0,NI) resp->aggI (mean, xi dst), [NI,NI+NS) rev->aggS (mean),
// [NI+NS, NI+2NS) prec->aggP (sum). Block 0 also zeroes colstats.
__global__ void k_gather3(
    const uint2* __restrict__ xsrcS,   // xs16 rows
    const uint2* __restrict__ xsrcI,   // xi16 rows
    const int* __restrict__ eResp, const int* __restrict__ oResp,
    const int* __restrict__ eRev,  const int* __restrict__ oRev,
    const int* __restrict__ ePrec, const int* __restrict__ oPrec,
    uint2* __restrict__ aggI, uint2* __restrict__ aggS, uint2* __restrict__ aggP,
    int NI, int NS, float* __restrict__ colstats) {
    if (blockIdx.x == 0 && threadIdx.x < 256) colstats[threadIdx.x] = 0.f;
    int w = (blockIdx.x * blockDim.x + threadIdx.x) >> 5;
    int lane = threadIdx.x & 31;
    const uint2* x; const int* edges; const int* off; uint2* out;
    int d, domean;
    if (w < NI)           { d = w;          x = xsrcS; edges = eResp; off = oResp; out = aggI; domean = 1; }
    else if (w < NI + NS) { d = w - NI;     x = xsrcI; edges = eRev;  off = oRev;  out = aggS; domean = 1; }
    else if (w < NI + 2 * NS) { d = w - NI - NS; x = xsrcS; edges = ePrec; off = oPrec; out = aggP; domean = 0; }
    else return;

    int beg = off[d], end = off[d + 1];
    float4 acc = make_float4(0.f, 0.f, 0.f, 0.f);
    for (int e = beg; e < end; e++) {
        int s = edges[e];
        uint2 u = __ldg(&x[(size_t)s * 32 + lane]);
        __half2 h0 = *reinterpret_cast<__half2*>(&u.x);
        __half2 h1 = *reinterpret_cast<__half2*>(&u.y);
        float2 f0 = __half22float2(h0);
        float2 f1 = __half22float2(h1);
        acc.x += f0.x; acc.y += f0.y; acc.z += f1.x; acc.w += f1.y;
    }
    if (domean) {
        int c = end - beg; if (c < 1) c = 1;
        float inv = 1.0f / (float)c;
        acc.x *= inv; acc.y *= inv; acc.z *= inv; acc.w *= inv;
    }
    uint2 o;
    o.x = pack_h2(acc.x, acc.y);
    o.y = pack_h2(acc.z, acc.w);
    out[(size_t)d * 32 + lane] = o;
}

// ---------------- FP16 tensor-core GEMM, cp.async 4-stage pipeline --------------
// (unchanged from round 8)
#define BK   32
#define LDW  20
#define TILEW (128 * LDW)

__device__ __forceinline__ void cp16(uint32_t dst, const void* src, int srcsize) {
    asm volatile("cp.async.cg.shared.global [%0], [%1], 16, %2;"
                 :: "r"(dst), "l"(src), "r"(srcsize));
}

__device__ __forceinline__ void mma_f16(float c[4],
                                        uint32_t a0, uint32_t a1, uint32_t a2, uint32_t a3,
                                        uint32_t b0, uint32_t b1) {
    asm volatile(
        "mma.sync.aligned.m16n8k16.row.col.f32.f16.f16.f32 "
        "{%0,%1,%2,%3}, {%4,%5,%6,%7}, {%8,%9}, {%0,%1,%2,%3};"
        : "+f"(c[0]), "+f"(c[1]), "+f"(c[2]), "+f"(c[3])
        : "r"(a0), "r"(a1), "r"(a2), "r"(a3), "r"(b0), "r"(b1));
}

__global__ __launch_bounds__(256, 2) void k_gemm_tc(
    const unsigned short* __restrict__ A0, const unsigned short* __restrict__ A1,
    const unsigned short* __restrict__ A2,
    const unsigned short* __restrict__ W0, const unsigned short* __restrict__ W1,
    const unsigned short* __restrict__ W2,
    const float* __restrict__ b0, const float* __restrict__ b1,
    float scale, int mode, int NA, int M,
    float* __restrict__ C, unsigned short* __restrict__ Cshadow,
    float* __restrict__ colsum, float* __restrict__ colsq) {

    extern __shared__ uint32_t smemu[];
    uint32_t* sA = smemu;
    uint32_t* sB = smemu + 4 * TILEW;
    __shared__ float ssum[128], ssq[128];

    const int tid  = threadIdx.x;
    const int m0   = blockIdx.x * 128;
    const int warp = tid >> 5;
    const int lane = tid & 31;
    const int wm   = warp >> 1;
    const int wn   = warp & 1;
    const int g    = lane >> 2;
    const int t4   = lane & 3;

    const int c0 = tid * 2;

    const unsigned short* Aarr[3] = {A0, A1, A2};
    const unsigned short* Warr[3] = {W0, W1, W2};

    const uint32_t sA_addr = (uint32_t)__cvta_generic_to_shared(sA);
    const uint32_t sB_addr = (uint32_t)__cvta_generic_to_shared(sB);

    float acc[2][8][4];
#pragma unroll
    for (int i = 0; i < 2; i++)
#pragma unroll
        for (int j = 0; j < 8; j++)
#pragma unroll
            for (int c = 0; c < 4; c++) acc[i][j][c] = 0.f;

    const int KT = NA * (D / BK);

    auto issue = [&](int t, int st) {
        int a  = t >> 2;
        int k0 = (t & 3) * BK;
        const unsigned short* A = Aarr[a];
        const unsigned short* W = Warr[a];
        uint32_t dA = sA_addr + st * (TILEW * 4);
        uint32_t dB = sB_addr + st * (TILEW * 4);
#pragma unroll
        for (int i = 0; i < 2; i++) {
            int c   = c0 + i;
            int row = c >> 2;
            int seg = c & 3;
            uint32_t doff = (uint32_t)(row * LDW + seg * 4) * 4;
            int szA = (m0 + row < M) ? 16 : 0;
            cp16(dA + doff, A + (size_t)(m0 + row) * D + k0 + seg * 8, szA);
            cp16(dB + doff, W + (size_t)row * D + k0 + seg * 8, 16);
        }
        asm volatile("cp.async.commit_group;");
    };

#pragma unroll
    for (int s = 0; s < 3; s++) issue(s, s);

    for (int t = 0; t < KT; t++) {
        asm volatile("cp.async.wait_group 2;");
        __syncthreads();

        if (t + 3 < KT) issue(t + 3, (t + 3) & 3);
        else asm volatile("cp.async.commit_group;");

        const uint32_t* cA = sA + (t & 3) * TILEW;
        const uint32_t* cB = sB + (t & 3) * TILEW;
#pragma unroll
        for (int kk2 = 0; kk2 < 2; kk2++) {
            const int wk = kk2 * 8;
            uint32_t af[2][4];
#pragma unroll
            for (int i = 0; i < 2; i++) {
                int mb = wm * 32 + i * 16;
                af[i][0] = cA[(mb + g)     * LDW + wk + t4];
                af[i][1] = cA[(mb + g + 8) * LDW + wk + t4];
                af[i][2] = cA[(mb + g)     * LDW + wk + t4 + 4];
                af[i][3] = cA[(mb + g + 8) * LDW + wk + t4 + 4];
            }
#pragma unroll
            for (int j = 0; j < 8; j++) {
                int nb = wn * 64 + j * 8;
                uint32_t bf0 = cB[(nb + g) * LDW + wk + t4];
                uint32_t bf1 = cB[(nb + g) * LDW + wk + t4 + 4];
                mma_f16(acc[0][j], af[0][0], af[0][1], af[0][2], af[0][3], bf0, bf1);
                mma_f16(acc[1][j], af[1][0], af[1][1], af[1][2], af[1][3], bf0, bf1);
            }
        }
        __syncthreads();
    }

    if (mode == 1) {
        if (tid < 128) { ssum[tid] = 0.f; ssq[tid] = 0.f; }
        __syncthreads();
    }

    float2 bias[8];
#pragma unroll
    for (int j = 0; j < 8; j++) {
        int col = wn * 64 + j * 8 + t4 * 2;
        bias[j].x = b0[col]     + (b1 ? b1[col]     : 0.f);
        bias[j].y = b0[col + 1] + (b1 ? b1[col + 1] : 0.f);
    }

    float ps[16], pq[16];
#pragma unroll
    for (int j = 0; j < 16; j++) { ps[j] = 0.f; pq[j] = 0.f; }

#pragma unroll
    for (int i = 0; i < 2; i++) {
        int row0 = m0 + wm * 32 + i * 16 + g;
        int row1 = row0 + 8;
#pragma unroll
        for (int j = 0; j < 8; j++) {
            int col = wn * 64 + j * 8 + t4 * 2;
            if (row0 < M) {
                float v0 = scale * (acc[i][j][0] + bias[j].x);
                float v1 = scale * (acc[i][j][1] + bias[j].y);
                if (mode == 1) {
                    v0 = (v0 > 0.f) ? v0 : expm1f(v0);
                    v1 = (v1 > 0.f) ? v1 : expm1f(v1);
                    ps[j * 2] += v0; pq[j * 2] += v0 * v0;
                    ps[j * 2 + 1] += v1; pq[j * 2 + 1] += v1 * v1;
                }
                *(float2*)(C + (size_t)row0 * D + col) = make_float2(v0, v1);
                if (Cshadow)
                    *(uint32_t*)(Cshadow + (size_t)row0 * D + col) = pack_h2(v0, v1);
            }
            if (row1 < M) {
                float v0 = scale * (acc[i][j][2] + bias[j].x);
                float v1 = scale * (acc[i][j][3] + bias[j].y);
                if (mode == 1) {
                    v0 = (v0 > 0.f) ? v0 : expm1f(v0);
                    v1 = (v1 > 0.f) ? v1 : expm1f(v1);
                    ps[j * 2] += v0; pq[j * 2] += v0 * v0;
                    ps[j * 2 + 1] += v1; pq[j * 2 + 1] += v1 * v1;
                }
                *(float2*)(C + (size_t)row1 * D + col) = make_float2(v0, v1);
                if (Cshadow)
                    *(uint32_t*)(Cshadow + (size_t)row1 * D + col) = pack_h2(v0, v1);
            }
        }
    }

    if (mode == 1) {
#pragma unroll
        for (int j = 0; j < 8; j++) {
            int col = wn * 64 + j * 8 + t4 * 2;
            atomicAdd(&ssum[col], ps[j * 2]);
            atomicAdd(&ssq[col], pq[j * 2]);
            atomicAdd(&ssum[col + 1], ps[j * 2 + 1]);
            atomicAdd(&ssq[col + 1], pq[j * 2 + 1]);
        }
        __syncthreads();
        if (tid < 128) {
            atomicAdd(&colsum[tid], ssum[tid]);
            atomicAdd(&colsq[tid], ssq[tid]);
        }
    }
}

// ---------------- batchnorm ----------------
__global__ void k_bn_prep(const float* __restrict__ stats, const float* __restrict__ g,
                          const float* __restrict__ b, float invN, float* __restrict__ ac) {
    int t = threadIdx.x;
    float m = stats[t] * invN;
    float var = stats[128 + t] * invN - m * m;
    float r = rsqrtf(var + 1e-5f);
    float a = g[t] * r;
    ac[t] = a;
    ac[128 + t] = b[t] - m * a;
}
__global__ void k_bn_apply(float4* __restrict__ x, int n4, const float* __restrict__ ac,
                           uint2* __restrict__ shadow) {
    __shared__ float sa[128], sc[128];
    if (threadIdx.x < 128) { sa[threadIdx.x] = ac[threadIdx.x]; sc[threadIdx.x] = ac[128 + threadIdx.x]; }
    __syncthreads();
    int stride = gridDim.x * blockDim.x;
    for (int i = blockIdx.x * blockDim.x + threadIdx.x; i < n4; i += stride) {
        float4 v = x[i];
        int c = (i & 31) * 4;
        v.x = v.x * sa[c + 0] + sc[c + 0];
        v.y = v.y * sa[c + 1] + sc[c + 1];
        v.z = v.z * sa[c + 2] + sc[c + 2];
        v.w = v.w * sa[c + 3] + sc[c + 3];
        x[i] = v;
        if (shadow) {
            uint2 u;
            u.x = pack_h2(v.x, v.y);
            u.y = pack_h2(v.z, v.w);
            shadow[i] = u;
        }
    }
}

// ---------------- host side ----------------
static void* sym_addr(const void* sym) {
    void* p = nullptr;
    cudaGetSymbolAddress(&p, sym);
    return p;
}

extern "C" void kernel_launch(void* const* d_in, const int* in_sizes, int n_in,
                              void* d_out, int out_size) {
    const float* x_student = (const float*)d_in[0];
    const float* x_item    = (const float*)d_in[1];
    const float* Wl_ri = (const float*)d_in[2];
    const float* bl_ri = (const float*)d_in[3];
    const float* Wr_ri = (const float*)d_in[4];
    const float* Wl_rs = (const float*)d_in[5];
    const float* bl_rs = (const float*)d_in[6];
    const float* Wr_rs = (const float*)d_in[7];
    const float* W_p   = (const float*)d_in[8];
    const float* b_p   = (const float*)d_in[9];
    const float* bn_g  = (const float*)d_in[10];
    const float* bn_b  = (const float*)d_in[11];
    const int* resp_src = (const int*)d_in[12];
    const int* resp_dst = (const int*)d_in[13];
    const int* rev_src  = (const int*)d_in[14];
    const int* rev_dst  = (const int*)d_in[15];
    const int* prec_src = (const int*)d_in[16];
    const int* prec_dst = (const int*)d_in[17];

    const int NS = in_sizes[0] / D;
    const int NI = in_sizes[1] / D;
    const int E1 = in_sizes[12];   // resp
    const int E2 = in_sizes[14];   // rev
    const int E3 = in_sizes[16];   // prec

    unsigned short* aggI = (unsigned short*)sym_addr(g_aggI);
    unsigned short* aggS = (unsigned short*)sym_addr(g_aggS);
    unsigned short* aggP = (unsigned short*)sym_addr(g_aggP);
    unsigned short* xs16 = (unsigned short*)sym_addr(g_xs16);
    unsigned short* xi16 = (unsigned short*)sym_addr(g_xi16);
    unsigned short* w_lri = (unsigned short*)sym_addr(g_w_lri);
    unsigned short* w_rri = (unsigned short*)sym_addr(g_w_rri);
    unsigned short* w_lrs = (unsigned short*)sym_addr(g_w_lrs);
    unsigned short* w_rrs = (unsigned short*)sym_addr(g_w_rrs);
    unsigned short* w_p   = (unsigned short*)sym_addr(g_w_p);
    int* off_resp  = (int*)sym_addr(g_off_resp);
    int* edge_resp = (int*)sym_addr(g_edge_resp);
    int* off_rev   = (int*)sym_addr(g_off_rev);
    int* edge_rev  = (int*)sym_addr(g_edge_rev);
    int* off_prec  = (int*)sym_addr(g_off_prec);
    int* edge_prec = (int*)sym_addr(g_edge_prec);
    int* cnt_resp  = (int*)sym_addr(g_cnt_resp);
    int* cnt_rev   = (int*)sym_addr(g_cnt_rev);
    int* cnt_prec  = (int*)sym_addr(g_cnt_prec);
    int* bsum      = (int*)sym_addr(g_bsum);
    float* colstats = (float*)sym_addr(g_colstats);
    float* bn_ac    = (float*)sym_addr(g_bn_ac);

    float* xi_out = (float*)d_out;                 // NI x D
    float* xs_out = xi_out + (size_t)NI * D;       // NS x D

    static int smem_set = 0;
    const int SMEM_DYN = 8 * TILEW * 4;  // 81920 B
    if (!smem_set) {
        cudaFuncSetAttribute(k_gemm_tc, cudaFuncAttributeMaxDynamicSharedMemorySize, SMEM_DYN);
        smem_set = 1;
    }

    // ---- fused CSR build for all three graphs ----
    const int Etot = E1 + E2 + E3;
    const int Ntot = NI + NS + NS;
    const int nb1 = (NI + 1023) / 1024;
    const int nb2 = (NS + 1023) / 1024;
    const int nb3 = (NS + 1023) / 1024;
    k_zero3<<<(Ntot + 255) / 256, 256>>>(cnt_resp, NI, cnt_rev, NS, cnt_prec, NS);
    k_count3<<<(Etot + 255) / 256, 256>>>(resp_dst, E1, cnt_resp,
                                          rev_dst, E2, cnt_rev,
                                          prec_dst, E3, cnt_prec);
    k_scan_block3<<<nb1 + nb2 + nb3, 1024>>>(cnt_resp, NI, off_resp, nb1,
                                             cnt_rev, NS, off_rev, nb2,
                                             cnt_prec, NS, off_prec, bsum);
    k_scan_bsum3<<<1, 1024>>>(bsum, nb1, nb2, nb3);
    k_scan_add3<<<nb1 + nb2 + nb3, 1024>>>(NI, off_resp, nb1,
                                           NS, off_rev, nb2,
                                           NS, off_prec, bsum);
    k_copy3<<<(Ntot + 255) / 256, 256>>>(cnt_resp, off_resp, NI,
                                         cnt_rev, off_rev, NS,
                                         cnt_prec, off_prec, NS);
    k_fill3<<<(Etot + 255) / 256, 256>>>(resp_src, resp_dst, E1, cnt_resp, edge_resp,
                                         rev_src, rev_dst, E2, cnt_rev, edge_rev,
                                         prec_src, prec_dst, E3, cnt_prec, edge_prec);

    // ---- fp16 shadows of inputs and weights (single launch) ----
    {
        int n4s = NS * D / 4, n4i = NI * D / 4, n4w = 2 * D * D / 4;
        int tot = n4s + n4i + 5 * n4w;
        k_cvt_all<<<(tot + 255) / 256, 256>>>(
            (const float4*)x_student, (const float4*)x_item,
            (const float4*)Wl_ri, (const float4*)Wr_ri,
            (const float4*)Wl_rs, (const float4*)Wr_rs, (const float4*)W_p,
            (uint2*)xs16, (uint2*)xi16,
            (uint2*)w_lri, (uint2*)w_rri,
            (uint2*)w_lrs, (uint2*)w_rrs, (uint2*)w_p,
            n4s, n4i, n4w);
    }

    const int gwTot = NI + 2 * NS;
    const int gBlocks = (gwTot + 7) / 8;    // 8 warps per 256-thread block
    const int gbI = (NI + 127) / 128;
    const int gbS = (NS + 127) / 128;

    for (int l = 0; l < 2; l++) {
        const size_t wOff = (size_t)l * D * D;
        const size_t bOff = (size_t)l * D;
        const int last = (l == 1);

        // fused gathers (read fp16 shadows, emit fp16); block 0 zeroes colstats
        k_gather3<<<gBlocks, 256>>>(
            (const uint2*)xs16, (const uint2*)xi16,
            edge_resp, off_resp, edge_rev, off_rev, edge_prec, off_prec,
            (uint2*)aggI, (uint2*)aggS, (uint2*)aggP,
            NI, NS, colstats);

        // item path: fp16 GEMM (K=256) + bias + ELU + BN stats
        k_gemm_tc<<<gbI, 256, SMEM_DYN>>>(aggI, xi16, nullptr,
                                          w_lri + wOff, w_rri + wOff, nullptr,
                                          bl_ri + bOff, nullptr,
                                          1.0f, 1, 2, NI, xi_out, nullptr,
                                          colstats, colstats + 128);
        k_bn_prep<<<1, 128>>>(colstats, bn_g + bOff, bn_b + bOff,
                              1.0f / (float)NI, bn_ac);
        k_bn_apply<<<512, 256>>>((float4*)xi_out, NI * 32, bn_ac,
                                 last ? nullptr : (uint2*)xi16);

        // student path: fp16 GEMM (K=384), out = 0.5*(sum + bl_rs + b_p)
        k_gemm_tc<<<gbS, 256, SMEM_DYN>>>(aggS, xs16, aggP,
                                          w_lrs + wOff, w_rrs + wOff, w_p + wOff,
                                          bl_rs + bOff, b_p + bOff,
                                          0.5f, 0, 3, NS, xs_out,
                                          last ? nullptr : xs16,
                                          nullptr, nullptr);
    }
}

// round 10
// speedup vs baseline: 2.5055x; 1.1374x over previous
#include <cuda_runtime.h>
#include <cuda_fp16.h>
#include <math.h>
#include <stdint.h>

#define D 128
#define NS_MAX 100000
#define NI_MAX 20000
#define E_MAX  600000

// ---------------- device scratch (static, no allocation) ----------------
__device__ unsigned short g_aggI[(size_t)NI_MAX * D];
__device__ unsigned short g_aggS[(size_t)NS_MAX * D];
__device__ unsigned short g_aggP[(size_t)NS_MAX * D];
__device__ unsigned short g_xs16[(size_t)NS_MAX * D];
__device__ unsigned short g_xi16[(size_t)NI_MAX * D];
__device__ unsigned short g_w_lri[2 * D * D];
__device__ unsigned short g_w_rri[2 * D * D];
__device__ unsigned short g_w_lrs[2 * D * D];
__device__ unsigned short g_w_rrs[2 * D * D];
__device__ unsigned short g_w_p[2 * D * D];

__device__ int g_off_resp[NI_MAX + 1];
__device__ int g_edge_resp[E_MAX];
__device__ int g_off_rev[NS_MAX + 1];
__device__ int g_edge_rev[E_MAX];
__device__ int g_off_prec[NS_MAX + 1];
__device__ int g_edge_prec[E_MAX];

__device__ int g_cnt_resp[NI_MAX];
__device__ int g_cnt_rev[NS_MAX];
__device__ int g_cnt_prec[NS_MAX];

__device__ int   g_bsum[1024];
__device__ float g_colstats[256];   // [0:128) sum, [128:256) sumsq
__device__ float g_bn_ac[256];      // [0:128) a,   [128:256) c

__device__ __forceinline__ uint32_t pack_h2(float a, float b) {
    __half2 h = __float22half2_rn(make_float2(a, b));
    return *(uint32_t*)&h;
}

// ---------------- fused conversion: all fp32 inputs -> fp16 shadows -------------
__global__ void k_cvt_all(
    const float4* __restrict__ xs, const float4* __restrict__ xi,
    const float4* __restrict__ w0, const float4* __restrict__ w1,
    const float4* __restrict__ w2, const float4* __restrict__ w3,
    const float4* __restrict__ w4,
    uint2* __restrict__ oxs, uint2* __restrict__ oxi,
    uint2* __restrict__ ow0, uint2* __restrict__ ow1,
    uint2* __restrict__ ow2, uint2* __restrict__ ow3,
    uint2* __restrict__ ow4,
    int n4s, int n4i, int n4w) {
    int i = blockIdx.x * blockDim.x + threadIdx.x;
    const float4* in; uint2* out; int j;
    if (i < n4s) { in = xs; out = oxs; j = i; }
    else {
        i -= n4s;
        if (i < n4i) { in = xi; out = oxi; j = i; }
        else {
            i -= n4i;
            int ws = i / n4w; j = i - ws * n4w;
            if (ws >= 5) return;
            switch (ws) {
                case 0: in = w0; out = ow0; break;
                case 1: in = w1; out = ow1; break;
                case 2: in = w2; out = ow2; break;
                case 3: in = w3; out = ow3; break;
                default: in = w4; out = ow4; break;
            }
        }
    }
    float4 v = in[j];
    uint2 u; u.x = pack_h2(v.x, v.y); u.y = pack_h2(v.z, v.w);
    out[j] = u;
}

// ---------------- fused CSR build (3 graphs) ----------------
__global__ void k_zero3(int* __restrict__ c1, int n1, int* __restrict__ c2, int n2,
                        int* __restrict__ c3, int n3) {
    int i = blockIdx.x * blockDim.x + threadIdx.x;
    if (i < n1) c1[i] = 0;
    else { i -= n1; if (i < n2) c2[i] = 0;
           else { i -= n2; if (i < n3) c3[i] = 0; } }
}
__global__ void k_count3(const int* __restrict__ d1, int E1, int* __restrict__ c1,
                         const int* __restrict__ d2, int E2, int* __restrict__ c2,
                         const int* __restrict__ d3, int E3, int* __restrict__ c3) {
    int i = blockIdx.x * blockDim.x + threadIdx.x;
    if (i < E1) atomicAdd(&c1[d1[i]], 1);
    else { i -= E1; if (i < E2) atomicAdd(&c2[d2[i]], 1);
           else { i -= E2; if (i < E3) atomicAdd(&c3[d3[i]], 1); } }
}
__global__ void k_scan_block3(
    const int* __restrict__ c1, int n1, int* __restrict__ o1, int nb1,
    const int* __restrict__ c2, int n2, int* __restrict__ o2, int nb2,
    const int* __restrict__ c3, int n3, int* __restrict__ o3,
    int* __restrict__ bsum) {
    __shared__ int sh[1024];
    int tid = threadIdx.x;
    int b = blockIdx.x;
    const int* cnt; int* off; int n; int lb;
    if (b < nb1)            { cnt = c1; off = o1; n = n1; lb = b; }
    else if (b < nb1 + nb2) { cnt = c2; off = o2; n = n2; lb = b - nb1; }
    else                    { cnt = c3; off = o3; n = n3; lb = b - nb1 - nb2; }
    int i = lb * 1024 + tid;
    int v = (i < n) ? cnt[i] : 0;
    sh[tid] = v;
    __syncthreads();
    for (int d = 1; d < 1024; d <<= 1) {
        int t = 0;
        if (tid >= d) t = sh[tid - d];
        __syncthreads();
        if (tid >= d) sh[tid] += t;
        __syncthreads();
    }
    if (i < n) off[i + 1] = sh[tid];
    if (tid == 1023) bsum[blockIdx.x] = sh[1023];
}
// exclusive scan of 3 bsum segments, scanned in parallel (nb<=128 each)
__global__ void k_scan_bsum3(int* __restrict__ bsum, int nb1, int nb2, int nb3) {
    __shared__ int sh[3][128];
    int seg = threadIdx.x >> 7;      // 384 threads: 3 segments x 128
    int t = threadIdx.x & 127;
    int base = (seg == 0) ? 0 : ((seg == 1) ? nb1 : nb1 + nb2);
    int nb = (seg == 0) ? nb1 : ((seg == 1) ? nb2 : nb3);
    int v = (t < nb) ? bsum[base + t] : 0;
    sh[seg][t] = v;
    __syncthreads();
    for (int d = 1; d < 128; d <<= 1) {
        int x = 0;
        if (t >= d) x = sh[seg][t - d];
        __syncthreads();
        if (t >= d) sh[seg][t] += x;
        __syncthreads();
    }
    if (t < nb) bsum[base + t] = sh[seg][t] - v;   // exclusive
}
// add block offsets; also write cursor (= final off) fused
__global__ void k_scan_add3(
    int n1, int* __restrict__ o1, int* __restrict__ c1, int nb1,
    int n2, int* __restrict__ o2, int* __restrict__ c2, int nb2,
    int n3, int* __restrict__ o3, int* __restrict__ c3,
    const int* __restrict__ bsum) {
    int b = blockIdx.x;
    int* off; int* cur; int n; int lb;
    if (b < nb1)            { off = o1; cur = c1; n = n1; lb = b; }
    else if (b < nb1 + nb2) { off = o2; cur = c2; n = n2; lb = b - nb1; }
    else                    { off = o3; cur = c3; n = n3; lb = b - nb1 - nb2; }
    int i = lb * 1024 + threadIdx.x;
    if (i < n) {
        int v = off[i + 1] + bsum[b];
        off[i + 1] = v;
        if (i + 1 < n) cur[i + 1] = v;
    }
    if (i == 0) { off[0] = 0; cur[0] = 0; }
}
__global__ void k_fill3(
    const int* __restrict__ s1, const int* __restrict__ d1, int E1,
    int* __restrict__ c1, int* __restrict__ e1,
    const int* __restrict__ s2, const int* __restrict__ d2, int E2,
    int* __restrict__ c2, int* __restrict__ e2,
    const int* __restrict__ s3, const int* __restrict__ d3, int E3,
    int* __restrict__ c3, int* __restrict__ e3) {
    int i = blockIdx.x * blockDim.x + threadIdx.x;
    if (i < E1) { int p = atomicAdd(&c1[d1[i]], 1); e1[p] = s1[i]; }
    else { i -= E1;
        if (i < E2) { int p = atomicAdd(&c2[d2[i]], 1); e2[p] = s2[i]; }
        else { i -= E2;
            if (i < E3) { int p = atomicAdd(&c3[d3[i]], 1); e3[p] = s3[i]; } } }
}

// ---------------- fused gather: 3 aggregations in one launch --------------------
__global__ void k_gather3(
    const uint2* __restrict__ xsrcS, const uint2* __restrict__ xsrcI,
    const int* __restrict__ eResp, const int* __restrict__ oResp,
    const int* __restrict__ eRev,  const int* __restrict__ oRev,
    const int* __restrict__ ePrec, const int* __restrict__ oPrec,
    uint2* __restrict__ aggI, uint2* __restrict__ aggS, uint2* __restrict__ aggP,
    int NI, int NS, float* __restrict__ colstats) {
    if (blockIdx.x == 0 && threadIdx.x < 256) colstats[threadIdx.x] = 0.f;
    int w = (blockIdx.x * blockDim.x + threadIdx.x) >> 5;
    int lane = threadIdx.x & 31;
    const uint2* x; const int* edges; const int* off; uint2* out;
    int d, domean;
    if (w < NI)           { d = w;          x = xsrcS; edges = eResp; off = oResp; out = aggI; domean = 1; }
    else if (w < NI + NS) { d = w - NI;     x = xsrcI; edges = eRev;  off = oRev;  out = aggS; domean = 1; }
    else if (w < NI + 2 * NS) { d = w - NI - NS; x = xsrcS; edges = ePrec; off = oPrec; out = aggP; domean = 0; }
    else return;

    int beg = off[d], end = off[d + 1];
    float4 acc = make_float4(0.f, 0.f, 0.f, 0.f);
    for (int e = beg; e < end; e++) {
        int s = edges[e];
        uint2 u = __ldg(&x[(size_t)s * 32 + lane]);
        __half2 h0 = *reinterpret_cast<__half2*>(&u.x);
        __half2 h1 = *reinterpret_cast<__half2*>(&u.y);
        float2 f0 = __half22float2(h0);
        float2 f1 = __half22float2(h1);
        acc.x += f0.x; acc.y += f0.y; acc.z += f1.x; acc.w += f1.y;
    }
    if (domean) {
        int c = end - beg; if (c < 1) c = 1;
        float inv = 1.0f / (float)c;
        acc.x *= inv; acc.y *= inv; acc.z *= inv; acc.w *= inv;
    }
    uint2 o;
    o.x = pack_h2(acc.x, acc.y);
    o.y = pack_h2(acc.z, acc.w);
    out[(size_t)d * 32 + lane] = o;
}

// ---------------- FP16 tensor-core GEMM (unchanged) ----------------
#define BK   32
#define LDW  20
#define TILEW (128 * LDW)

__device__ __forceinline__ void cp16(uint32_t dst, const void* src, int srcsize) {
    asm volatile("cp.async.cg.shared.global [%0], [%1], 16, %2;"
                 :: "r"(dst), "l"(src), "r"(srcsize));
}

__device__ __forceinline__ void mma_f16(float c[4],
                                        uint32_t a0, uint32_t a1, uint32_t a2, uint32_t a3,
                                        uint32_t b0, uint32_t b1) {
    asm volatile(
        "mma.sync.aligned.m16n8k16.row.col.f32.f16.f16.f32 "
        "{%0,%1,%2,%3}, {%4,%5,%6,%7}, {%8,%9}, {%0,%1,%2,%3};"
        : "+f"(c[0]), "+f"(c[1]), "+f"(c[2]), "+f"(c[3])
        : "r"(a0), "r"(a1), "r"(a2), "r"(a3), "r"(b0), "r"(b1));
}

__global__ __launch_bounds__(256, 2) void k_gemm_tc(
    const unsigned short* __restrict__ A0, const unsigned short* __restrict__ A1,
    const unsigned short* __restrict__ A2,
    const unsigned short* __restrict__ W0, const unsigned short* __restrict__ W1,
    const unsigned short* __restrict__ W2,
    const float* __restrict__ b0, const float* __restrict__ b1,
    float scale, int mode, int NA, int M,
    float* __restrict__ C, unsigned short* __restrict__ Cshadow,
    float* __restrict__ colsum, float* __restrict__ colsq) {

    extern __shared__ uint32_t smemu[];
    uint32_t* sA = smemu;
    uint32_t* sB = smemu + 4 * TILEW;
    __shared__ float ssum[128], ssq[128];

    const int tid  = threadIdx.x;
    const int m0   = blockIdx.x * 128;
    const int warp = tid >> 5;
    const int lane = tid & 31;
    const int wm   = warp >> 1;
    const int wn   = warp & 1;
    const int g    = lane >> 2;
    const int t4   = lane & 3;

    const int c0 = tid * 2;

    const unsigned short* Aarr[3] = {A0, A1, A2};
    const unsigned short* Warr[3] = {W0, W1, W2};

    const uint32_t sA_addr = (uint32_t)__cvta_generic_to_shared(sA);
    const uint32_t sB_addr = (uint32_t)__cvta_generic_to_shared(sB);

    float acc[2][8][4];
#pragma unroll
    for (int i = 0; i < 2; i++)
#pragma unroll
        for (int j = 0; j < 8; j++)
#pragma unroll
            for (int c = 0; c < 4; c++) acc[i][j][c] = 0.f;

    const int KT = NA * (D / BK);

    auto issue = [&](int t, int st) {
        int a  = t >> 2;
        int k0 = (t & 3) * BK;
        const unsigned short* A = Aarr[a];
        const unsigned short* W = Warr[a];
        uint32_t dA = sA_addr + st * (TILEW * 4);
        uint32_t dB = sB_addr + st * (TILEW * 4);
#pragma unroll
        for (int i = 0; i < 2; i++) {
            int c   = c0 + i;
            int row = c >> 2;
            int seg = c & 3;
            uint32_t doff = (uint32_t)(row * LDW + seg * 4) * 4;
            int szA = (m0 + row < M) ? 16 : 0;
            cp16(dA + doff, A + (size_t)(m0 + row) * D + k0 + seg * 8, szA);
            cp16(dB + doff, W + (size_t)row * D + k0 + seg * 8, 16);
        }
        asm volatile("cp.async.commit_group;");
    };

#pragma unroll
    for (int s = 0; s < 3; s++) issue(s, s);

    for (int t = 0; t < KT; t++) {
        asm volatile("cp.async.wait_group 2;");
        __syncthreads();

        if (t + 3 < KT) issue(t + 3, (t + 3) & 3);
        else asm volatile("cp.async.commit_group;");

        const uint32_t* cA = sA + (t & 3) * TILEW;
        const uint32_t* cB = sB + (t & 3) * TILEW;
#pragma unroll
        for (int kk2 = 0; kk2 < 2; kk2++) {
            const int wk = kk2 * 8;
            uint32_t af[2][4];
#pragma unroll
            for (int i = 0; i < 2; i++) {
                int mb = wm * 32 + i * 16;
                af[i][0] = cA[(mb + g)     * LDW + wk + t4];
                af[i][1] = cA[(mb + g + 8) * LDW + wk + t4];
                af[i][2] = cA[(mb + g)     * LDW + wk + t4 + 4];
                af[i][3] = cA[(mb + g + 8) * LDW + wk + t4 + 4];
            }
#pragma unroll
            for (int j = 0; j < 8; j++) {
                int nb = wn * 64 + j * 8;
                uint32_t bf0 = cB[(nb + g) * LDW + wk + t4];
                uint32_t bf1 = cB[(nb + g) * LDW + wk + t4 + 4];
                mma_f16(acc[0][j], af[0][0], af[0][1], af[0][2], af[0][3], bf0, bf1);
                mma_f16(acc[1][j], af[1][0], af[1][1], af[1][2], af[1][3], bf0, bf1);
            }
        }
        __syncthreads();
    }

    if (mode == 1) {
        if (tid < 128) { ssum[tid] = 0.f; ssq[tid] = 0.f; }
        __syncthreads();
    }

    float2 bias[8];
#pragma unroll
    for (int j = 0; j < 8; j++) {
        int col = wn * 64 + j * 8 + t4 * 2;
        bias[j].x = b0[col]     + (b1 ? b1[col]     : 0.f);
        bias[j].y = b0[col + 1] + (b1 ? b1[col + 1] : 0.f);
    }

    float ps[16], pq[16];
#pragma unroll
    for (int j = 0; j < 16; j++) { ps[j] = 0.f; pq[j] = 0.f; }

#pragma unroll
    for (int i = 0; i < 2; i++) {
        int row0 = m0 + wm * 32 + i * 16 + g;
        int row1 = row0 + 8;
#pragma unroll
        for (int j = 0; j < 8; j++) {
            int col = wn * 64 + j * 8 + t4 * 2;
            if (row0 < M) {
                float v0 = scale * (acc[i][j][0] + bias[j].x);
                float v1 = scale * (acc[i][j][1] + bias[j].y);
                if (mode == 1) {
                    v0 = (v0 > 0.f) ? v0 : expm1f(v0);
                    v1 = (v1 > 0.f) ? v1 : expm1f(v1);
                    ps[j * 2] += v0; pq[j * 2] += v0 * v0;
                    ps[j * 2 + 1] += v1; pq[j * 2 + 1] += v1 * v1;
                }
                *(float2*)(C + (size_t)row0 * D + col) = make_float2(v0, v1);
                if (Cshadow)
                    *(uint32_t*)(Cshadow + (size_t)row0 * D + col) = pack_h2(v0, v1);
            }
            if (row1 < M) {
                float v0 = scale * (acc[i][j][2] + bias[j].x);
                float v1 = scale * (acc[i][j][3] + bias[j].y);
                if (mode == 1) {
                    v0 = (v0 > 0.f) ? v0 : expm1f(v0);
                    v1 = (v1 > 0.f) ? v1 : expm1f(v1);
                    ps[j * 2] += v0; pq[j * 2] += v0 * v0;
                    ps[j * 2 + 1] += v1; pq[j * 2 + 1] += v1 * v1;
                }
                *(float2*)(C + (size_t)row1 * D + col) = make_float2(v0, v1);
                if (Cshadow)
                    *(uint32_t*)(Cshadow + (size_t)row1 * D + col) = pack_h2(v0, v1);
            }
        }
    }

    if (mode == 1) {
#pragma unroll
        for (int j = 0; j < 8; j++) {
            int col = wn * 64 + j * 8 + t4 * 2;
            atomicAdd(&ssum[col], ps[j * 2]);
            atomicAdd(&ssq[col], pq[j * 2]);
            atomicAdd(&ssum[col + 1], ps[j * 2 + 1]);
            atomicAdd(&ssq[col + 1], pq[j * 2 + 1]);
        }
        __syncthreads();
        if (tid < 128) {
            atomicAdd(&colsum[tid], ssum[tid]);
            atomicAdd(&colsq[tid], ssq[tid]);
        }
    }
}

// ---------------- batchnorm ----------------
__global__ void k_bn_prep(const float* __restrict__ stats, const float* __restrict__ g,
                          const float* __restrict__ b, float invN, float* __restrict__ ac) {
    int t = threadIdx.x;
    float m = stats[t] * invN;
    float var = stats[128 + t] * invN - m * m;
    float r = rsqrtf(var + 1e-5f);
    float a = g[t] * r;
    ac[t] = a;
    ac[128 + t] = b[t] - m * a;
}
__global__ void k_bn_apply(float4* __restrict__ x, int n4, const float* __restrict__ ac,
                           uint2* __restrict__ shadow) {
    __shared__ float sa[128], sc[128];
    if (threadIdx.x < 128) { sa[threadIdx.x] = ac[threadIdx.x]; sc[threadIdx.x] = ac[128 + threadIdx.x]; }
    __syncthreads();
    int stride = gridDim.x * blockDim.x;
    for (int i = blockIdx.x * blockDim.x + threadIdx.x; i < n4; i += stride) {
        float4 v = x[i];
        int c = (i & 31) * 4;
        v.x = v.x * sa[c + 0] + sc[c + 0];
        v.y = v.y * sa[c + 1] + sc[c + 1];
        v.z = v.z * sa[c + 2] + sc[c + 2];
        v.w = v.w * sa[c + 3] + sc[c + 3];
        x[i] = v;
        if (shadow) {
            uint2 u;
            u.x = pack_h2(v.x, v.y);
            u.y = pack_h2(v.z, v.w);
            shadow[i] = u;
        }
    }
}

// ---------------- host side ----------------
static void* sym_addr(const void* sym) {
    void* p = nullptr;
    cudaGetSymbolAddress(&p, sym);
    return p;
}

extern "C" void kernel_launch(void* const* d_in, const int* in_sizes, int n_in,
                              void* d_out, int out_size) {
    const float* x_student = (const float*)d_in[0];
    const float* x_item    = (const float*)d_in[1];
    const float* Wl_ri = (const float*)d_in[2];
    const float* bl_ri = (const float*)d_in[3];
    const float* Wr_ri = (const float*)d_in[4];
    const float* Wl_rs = (const float*)d_in[5];
    const float* bl_rs = (const float*)d_in[6];
    const float* Wr_rs = (const float*)d_in[7];
    const float* W_p   = (const float*)d_in[8];
    const float* b_p   = (const float*)d_in[9];
    const float* bn_g  = (const float*)d_in[10];
    const float* bn_b  = (const float*)d_in[11];
    const int* resp_src = (const int*)d_in[12];
    const int* resp_dst = (const int*)d_in[13];
    const int* rev_src  = (const int*)d_in[14];
    const int* rev_dst  = (const int*)d_in[15];
    const int* prec_src = (const int*)d_in[16];
    const int* prec_dst = (const int*)d_in[17];

    const int NS = in_sizes[0] / D;
    const int NI = in_sizes[1] / D;
    const int E1 = in_sizes[12];
    const int E2 = in_sizes[14];
    const int E3 = in_sizes[16];

    unsigned short* aggI = (unsigned short*)sym_addr(g_aggI);
    unsigned short* aggS = (unsigned short*)sym_addr(g_aggS);
    unsigned short* aggP = (unsigned short*)sym_addr(g_aggP);
    unsigned short* xs16 = (unsigned short*)sym_addr(g_xs16);
    unsigned short* xi16 = (unsigned short*)sym_addr(g_xi16);
    unsigned short* w_lri = (unsigned short*)sym_addr(g_w_lri);
    unsigned short* w_rri = (unsigned short*)sym_addr(g_w_rri);
    unsigned short* w_lrs = (unsigned short*)sym_addr(g_w_lrs);
    unsigned short* w_rrs = (unsigned short*)sym_addr(g_w_rrs);
    unsigned short* w_p   = (unsigned short*)sym_addr(g_w_p);
    int* off_resp  = (int*)sym_addr(g_off_resp);
    int* edge_resp = (int*)sym_addr(g_edge_resp);
    int* off_rev   = (int*)sym_addr(g_off_rev);
    int* edge_rev  = (int*)sym_addr(g_edge_rev);
    int* off_prec  = (int*)sym_addr(g_off_prec);
    int* edge_prec = (int*)sym_addr(g_edge_prec);
    int* cnt_resp  = (int*)sym_addr(g_cnt_resp);
    int* cnt_rev   = (int*)sym_addr(g_cnt_rev);
    int* cnt_prec  = (int*)sym_addr(g_cnt_prec);
    int* bsum      = (int*)sym_addr(g_bsum);
    float* colstats = (float*)sym_addr(g_colstats);
    float* bn_ac    = (float*)sym_addr(g_bn_ac);

    float* xi_out = (float*)d_out;                 // NI x D
    float* xs_out = xi_out + (size_t)NI * D;       // NS x D

    // one-time resources (host-side; no device allocation)
    static int init_done = 0;
    static cudaStream_t s2;
    static cudaEvent_t ev_fork, ev_cvt, ev_g, ev_j;
    const int SMEM_DYN = 8 * TILEW * 4;  // 81920 B
    if (!init_done) {
        cudaFuncSetAttribute(k_gemm_tc, cudaFuncAttributeMaxDynamicSharedMemorySize, SMEM_DYN);
        cudaStreamCreateWithFlags(&s2, cudaStreamNonBlocking);
        cudaEventCreateWithFlags(&ev_fork, cudaEventDisableTiming);
        cudaEventCreateWithFlags(&ev_cvt, cudaEventDisableTiming);
        cudaEventCreateWithFlags(&ev_g, cudaEventDisableTiming);
        cudaEventCreateWithFlags(&ev_j, cudaEventDisableTiming);
        init_done = 1;
    }

    // ---- fork: cvt_all on s2, concurrent with CSR build on main stream ----
    cudaEventRecord(ev_fork, 0);
    cudaStreamWaitEvent(s2, ev_fork, 0);
    {
        int n4s = NS * D / 4, n4i = NI * D / 4, n4w = 2 * D * D / 4;
        int tot = n4s + n4i + 5 * n4w;
        k_cvt_all<<<(tot + 255) / 256, 256, 0, s2>>>(
            (const float4*)x_student, (const float4*)x_item,
            (const float4*)Wl_ri, (const float4*)Wr_ri,
            (const float4*)Wl_rs, (const float4*)Wr_rs, (const float4*)W_p,
            (uint2*)xs16, (uint2*)xi16,
            (uint2*)w_lri, (uint2*)w_rri,
            (uint2*)w_lrs, (uint2*)w_rrs, (uint2*)w_p,
            n4s, n4i, n4w);
    }
    cudaEventRecord(ev_cvt, s2);

    // ---- fused CSR build (main stream) ----
    const int Etot = E1 + E2 + E3;
    const int Ntot = NI + NS + NS;
    const int nb1 = (NI + 1023) / 1024;
    const int nb2 = (NS + 1023) / 1024;
    const int nb3 = (NS + 1023) / 1024;
    k_zero3<<<(Ntot + 255) / 256, 256>>>(cnt_resp, NI, cnt_rev, NS, cnt_prec, NS);
    k_count3<<<(Etot + 255) / 256, 256>>>(resp_dst, E1, cnt_resp,
                                          rev_dst, E2, cnt_rev,
                                          prec_dst, E3, cnt_prec);
    k_scan_block3<<<nb1 + nb2 + nb3, 1024>>>(cnt_resp, NI, off_resp, nb1,
                                             cnt_rev, NS, off_rev, nb2,
                                             cnt_prec, NS, off_prec, bsum);
    k_scan_bsum3<<<1, 384>>>(bsum, nb1, nb2, nb3);
    k_scan_add3<<<nb1 + nb2 + nb3, 1024>>>(NI, off_resp, cnt_resp, nb1,
                                           NS, off_rev, cnt_rev, nb2,
                                           NS, off_prec, cnt_prec, bsum);
    k_fill3<<<(Etot + 255) / 256, 256>>>(resp_src, resp_dst, E1, cnt_resp, edge_resp,
                                         rev_src, rev_dst, E2, cnt_rev, edge_rev,
                                         prec_src, prec_dst, E3, cnt_prec, edge_prec);

    // join cvt before first gather
    cudaStreamWaitEvent(0, ev_cvt, 0);

    const int gwTot = NI + 2 * NS;
    const int gBlocks = (gwTot + 7) / 8;
    const int gbI = (NI + 127) / 128;
    const int gbS = (NS + 127) / 128;

    for (int l = 0; l < 2; l++) {
        const size_t wOff = (size_t)l * D * D;
        const size_t bOff = (size_t)l * D;
        const int last = (l == 1);

        // fused gathers (main stream); block 0 zeroes colstats
        k_gather3<<<gBlocks, 256>>>(
            (const uint2*)xs16, (const uint2*)xi16,
            edge_resp, off_resp, edge_rev, off_rev, edge_prec, off_prec,
            (uint2*)aggI, (uint2*)aggS, (uint2*)aggP,
            NI, NS, colstats);
        cudaEventRecord(ev_g, 0);

        // --- branch A (s2): item path (GEMM + BN) ---
        cudaStreamWaitEvent(s2, ev_g, 0);
        k_gemm_tc<<<gbI, 256, SMEM_DYN, s2>>>(aggI, xi16, nullptr,
                                              w_lri + wOff, w_rri + wOff, nullptr,
                                              bl_ri + bOff, nullptr,
                                              1.0f, 1, 2, NI, xi_out, nullptr,
                                              colstats, colstats + 128);
        k_bn_prep<<<1, 128, 0, s2>>>(colstats, bn_g + bOff, bn_b + bOff,
                                     1.0f / (float)NI, bn_ac);
        k_bn_apply<<<512, 256, 0, s2>>>((float4*)xi_out, NI * 32, bn_ac,
                                        last ? nullptr : (uint2*)xi16);
        cudaEventRecord(ev_j, s2);

        // --- branch B (main): student GEMM ---
        k_gemm_tc<<<gbS, 256, SMEM_DYN>>>(aggS, xs16, aggP,
                                          w_lrs + wOff, w_rrs + wOff, w_p + wOff,
                                          bl_rs + bOff, b_p + bOff,
                                          0.5f, 0, 3, NS, xs_out,
                                          last ? nullptr : xs16,
                                          nullptr, nullptr);

        // join branch A before next layer's gather (and before return)
        cudaStreamWaitEvent(0, ev_j, 0);
    }
}